// round 10
// baseline (speedup 1.0000x reference)
#include <cuda_runtime.h>
#include <math.h>

#define NN 50000
#define NE 800000
#define DD 128
#define ED 16
#define SCAN_NBLK ((NN + 1023) / 1024)   // 49
#define NCHUNK (NE / 128)                // 6250 (exact)

// Scratch (allocation-free rule: __device__ globals)
__device__ float g_bufA[NN * DD];
__device__ float g_bufB[NN * DD];
__device__ int   g_idx64;
__device__ int   g_cnt[NN];
__device__ int   g_rowptr[NN + 1];
__device__ int   g_cursor[NN];
__device__ int   g_blocksum[SCAN_NBLK];
__device__ int   g_blockoff[SCAN_NBLK];
__device__ int   g_src[NE];              // src node, dst-sorted
__device__ int   g_dstc[NE];             // dst node, dst-sorted (== sorted)
__device__ float g_eattr[NE * ED];       // edge_attr rows in dst-sorted order

// ---------------------------------------------------------------------------
// tf32 helpers
// ---------------------------------------------------------------------------
__device__ __forceinline__ void tf32split(float v, unsigned& hi, unsigned& lo) {
    asm("cvt.rna.tf32.f32 %0, %1;" : "=r"(hi) : "f"(v));
    float r = v - __uint_as_float(hi);
    asm("cvt.rna.tf32.f32 %0, %1;" : "=r"(lo) : "f"(r));
}

__device__ __forceinline__ void mma_tf32(float* d, const unsigned* a, const unsigned* b) {
    asm volatile(
        "mma.sync.aligned.m16n8k8.row.col.f32.tf32.tf32.f32 "
        "{%0,%1,%2,%3}, {%4,%5,%6,%7}, {%8,%9}, {%0,%1,%2,%3};"
        : "+f"(d[0]), "+f"(d[1]), "+f"(d[2]), "+f"(d[3])
        : "r"(a[0]), "r"(a[1]), "r"(a[2]), "r"(a[3]), "r"(b[0]), "r"(b[1]));
}

// ---------------------------------------------------------------------------
// Detect int64 vs int32 edge_idx (one warp, ballot)
// ---------------------------------------------------------------------------
__global__ void detect_idx_kernel(const long long* __restrict__ idx) {
    int lane = threadIdx.x;
    long long v = idx[lane];
    int bad = (v < 0 || v >= (long long)NN) ? 1 : 0;
    unsigned m = __ballot_sync(0xffffffffu, bad);
    if (lane == 0) g_idx64 = (m == 0u);
}

// ---------------------------------------------------------------------------
// CSR build
// ---------------------------------------------------------------------------
__global__ void zero_cnt_kernel() {
    int i = blockIdx.x * blockDim.x + threadIdx.x;
    if (i < NN) g_cnt[i] = 0;
}

__global__ void hist_kernel(const void* __restrict__ edge_idx) {
    int e = blockIdx.x * blockDim.x + threadIdx.x;
    if (e >= NE) return;
    int dst;
    if (g_idx64) dst = (int)((const long long*)edge_idx)[NE + e];
    else         dst = ((const int*)edge_idx)[NE + e];
    atomicAdd(&g_cnt[dst], 1);
}

__global__ void local_scan_kernel() {
    __shared__ int sdata[1024];
    int i = blockIdx.x * 1024 + threadIdx.x;
    int v = (i < NN) ? g_cnt[i] : 0;
    sdata[threadIdx.x] = v;
    __syncthreads();
    #pragma unroll
    for (int off = 1; off < 1024; off <<= 1) {
        int t = (threadIdx.x >= off) ? sdata[threadIdx.x - off] : 0;
        __syncthreads();
        sdata[threadIdx.x] += t;
        __syncthreads();
    }
    if (i < NN) g_rowptr[i] = sdata[threadIdx.x] - v;   // local exclusive
    if (threadIdx.x == 1023) g_blocksum[blockIdx.x] = sdata[1023];
}

__global__ void scan_sums_kernel() {
    __shared__ int sd[64];
    int t = threadIdx.x;
    int v = (t < SCAN_NBLK) ? g_blocksum[t] : 0;
    sd[t] = v;
    __syncthreads();
    #pragma unroll
    for (int off = 1; off < 64; off <<= 1) {
        int u = (t >= off) ? sd[t - off] : 0;
        __syncthreads();
        sd[t] += u;
        __syncthreads();
    }
    if (t < SCAN_NBLK) g_blockoff[t] = sd[t] - v;   // exclusive
}

__global__ void add_off_kernel() {
    int i = blockIdx.x * 1024 + threadIdx.x;
    if (i < NN) {
        int v = g_rowptr[i] + g_blockoff[blockIdx.x];
        g_rowptr[i] = v;
        g_cursor[i] = v;
    }
    if (i == 0) g_rowptr[NN] = NE;
}

// Fused scatter: src, dst AND attr row into dst-sorted order.
__global__ void scatter_fused_kernel(const void* __restrict__ edge_idx,
                                     const float* __restrict__ edge_attr) {
    int e = blockIdx.x * blockDim.x + threadIdx.x;
    if (e >= NE) return;
    int src, dst;
    if (g_idx64) {
        src = (int)((const long long*)edge_idx)[e];
        dst = (int)((const long long*)edge_idx)[NE + e];
    } else {
        src = ((const int*)edge_idx)[e];
        dst = ((const int*)edge_idx)[NE + e];
    }
    const float4* ea = (const float4*)(edge_attr + (size_t)e * ED);
    float4 a0 = ea[0], a1 = ea[1], a2 = ea[2], a3 = ea[3];
    int pos = atomicAdd(&g_cursor[dst], 1);
    g_src[pos] = src;
    g_dstc[pos] = dst;
    float4* dstp = (float4*)(g_eattr + (size_t)pos * ED);
    dstp[0] = a0; dstp[1] = a1; dstp[2] = a2; dstp[3] = a3;
}

// aggr = (1 + eps[l]) * xin
__global__ void init_aggr_kernel(const float* __restrict__ xin,
                                 const float* __restrict__ eps, int l,
                                 float* __restrict__ out) {
    float s = 1.0f + eps[l];
    const float4* x4 = (const float4*)xin;
    float4* o4 = (float4*)out;
    int total = NN * DD / 4;
    for (int i = blockIdx.x * blockDim.x + threadIdx.x; i < total;
         i += gridDim.x * blockDim.x) {
        float4 v = x4[i];
        o4[i] = make_float4(v.x * s, v.y * s, v.z * s, v.w * s);
    }
}

// ---------------------------------------------------------------------------
// Tensor-core edge phase: one block per 128-edge chunk (edges dst-sorted).
//   E = attr_chunk @ We          (tf32 3-split mma, M=128, K=16, N=128)
//   msg = relu(E + be + x[src])  (x rows pre-gathered coalesced into smem)
//   segmented sum over dst runs -> atomicAdd(float4) into aggr
// Fragment layouts identical to validated mlp_kernel.
// ---------------------------------------------------------------------------
#define XP 132      // sX pitch
#define AP 20       // attr / WeT pitch (conflict-free for (g,c) pattern)
#define AGG_SMEM_FLOATS (128 * XP + 128 * AP + 128 * AP + 128 + 128)
#define AGG_SMEM_BYTES (AGG_SMEM_FLOATS * 4 + 512)

__global__ void __launch_bounds__(256)
aggr_tc_kernel(const float* __restrict__ xin,
               const float* __restrict__ We,
               const float* __restrict__ be,
               float* __restrict__ aggr) {
    extern __shared__ float sm[];
    float* sX   = sm;                        // 128 x 132 : x[src] rows, then msg
    float* sAt  = sm + 128 * XP;             // 128 x 20 : attr chunk [edge][k]
    float* sWeT = sAt + 128 * AP;            // 128 x 20 : We^T [n][k]
    float* sBe  = sWeT + 128 * AP;           // 128
    float* sEps = sBe + 128;                 // (unused pad)
    int*   sDst = (int*)(sEps + 128);        // 128

    int tid = threadIdx.x;
    int lane = tid & 31, wid = tid >> 5;
    int e0 = blockIdx.x * 128;

    // ---- stage 1: loads ----
    // We^T + be
    for (int i = tid; i < ED * DD; i += 256) {
        int k = i >> 7, n = i & 127;          // coalesced over n
        sWeT[n * AP + k] = We[i];
    }
    if (tid < 128) sBe[tid] = be[tid];
    // attr chunk -> pitch-20
    for (int i = tid; i < 128 * 4; i += 256) {   // 512 float4
        int r = i >> 2, q = i & 3;
        float4 v = ((const float4*)(g_eattr + (size_t)(e0 + r) * ED))[q];
        *(float4*)(sAt + r * AP + q * 4) = v;
    }
    // dst ids
    if (tid < 128) sDst[tid] = g_dstc[e0 + tid];
    // x[src] rows, warp-per-row (coalesced 512B)
    for (int r = wid; r < 128; r += 8) {
        int src = g_src[e0 + r];
        float4 v = *(const float4*)(xin + (size_t)src * DD + lane * 4);
        *(float4*)(sX + r * XP + lane * 4) = v;
    }
    __syncthreads();

    // ---- stage 2: MMA (warp grid 4m x 2n; 2 mt x 8 j; K=16 -> 2 steps) ----
    int g = lane >> 2, c = lane & 3;
    int wm = wid & 3, wn = wid >> 2;
    int mrow = wm * 32, ncol = wn * 64;

    float acc[2][8][4];
    #pragma unroll
    for (int mt = 0; mt < 2; mt++)
        #pragma unroll
        for (int j = 0; j < 8; j++)
            #pragma unroll
            for (int q = 0; q < 4; q++) acc[mt][j][q] = 0.0f;

    #pragma unroll
    for (int s = 0; s < 2; s++) {
        int k0 = s * 8;
        unsigned bhi[8][2], blo[8][2];
        #pragma unroll
        for (int j = 0; j < 8; j++) {
            const float* bp = sWeT + (ncol + 8 * j + g) * AP + k0;
            tf32split(bp[c],     bhi[j][0], blo[j][0]);
            tf32split(bp[c + 4], bhi[j][1], blo[j][1]);
        }
        unsigned ahi[2][4], alo[2][4];
        #pragma unroll
        for (int mt = 0; mt < 2; mt++) {
            int r = mrow + mt * 16 + g;
            const float* a0p = sAt + r * AP + k0;
            const float* a1p = sAt + (r + 8) * AP + k0;
            tf32split(a0p[c],     ahi[mt][0], alo[mt][0]);
            tf32split(a1p[c],     ahi[mt][1], alo[mt][1]);
            tf32split(a0p[c + 4], ahi[mt][2], alo[mt][2]);
            tf32split(a1p[c + 4], ahi[mt][3], alo[mt][3]);
        }
        #pragma unroll
        for (int mt = 0; mt < 2; mt++)
            #pragma unroll
            for (int j = 0; j < 8; j++) mma_tf32(acc[mt][j], ahi[mt], bhi[j]);
        #pragma unroll
        for (int mt = 0; mt < 2; mt++)
            #pragma unroll
            for (int j = 0; j < 8; j++) mma_tf32(acc[mt][j], ahi[mt], blo[j]);
        #pragma unroll
        for (int mt = 0; mt < 2; mt++)
            #pragma unroll
            for (int j = 0; j < 8; j++) mma_tf32(acc[mt][j], alo[mt], bhi[j]);
    }

    // ---- stage 3: epilogue msg = relu(E + be + x[src]) in place into sX ----
    #pragma unroll
    for (int mt = 0; mt < 2; mt++) {
        int r = mrow + mt * 16 + g;
        #pragma unroll
        for (int j = 0; j < 8; j++) {
            int col = ncol + 8 * j + 2 * c;
            float2 x0 = *(float2*)(sX + r * XP + col);
            float2 x1 = *(float2*)(sX + (r + 8) * XP + col);
            float h0 = fmaxf(acc[mt][j][0] + sBe[col]     + x0.x, 0.0f);
            float h1 = fmaxf(acc[mt][j][1] + sBe[col + 1] + x0.y, 0.0f);
            float h2 = fmaxf(acc[mt][j][2] + sBe[col]     + x1.x, 0.0f);
            float h3 = fmaxf(acc[mt][j][3] + sBe[col + 1] + x1.y, 0.0f);
            *(float2*)(sX + r * XP + col) = make_float2(h0, h1);
            *(float2*)(sX + (r + 8) * XP + col) = make_float2(h2, h3);
        }
    }
    __syncthreads();

    // ---- stage 4: segmented reduction, warp w owns rows [16w, 16w+16) ----
    {
        int rbeg = wid * 16, rend = rbeg + 16;
        int c0 = lane * 4;
        int cur = sDst[rbeg];
        float4 a = *(float4*)(sX + rbeg * XP + c0);
        for (int r = rbeg + 1; r < rend; r++) {
            int d = sDst[r];
            float4 v = *(float4*)(sX + r * XP + c0);
            if (d != cur) {
                atomicAdd((float4*)(aggr + (size_t)cur * DD + c0), a);
                cur = d;
                a = v;
            } else {
                a.x += v.x; a.y += v.y; a.z += v.z; a.w += v.w;
            }
        }
        atomicAdd((float4*)(aggr + (size_t)cur * DD + c0), a);
    }
}

// ---------------------------------------------------------------------------
// Fused node MLP with tf32 tensor cores (3-way split) — unchanged from R9.
// ---------------------------------------------------------------------------
#define PITCH 132
#define MLP_TILES ((NN + 127) / 128)     // 391
#define MLP_SMEM_FLOATS (3 * 128 * PITCH + 256)
#define MLP_SMEM_BYTES (MLP_SMEM_FLOATS * 4)

__global__ void __launch_bounds__(512)
mlp_kernel(const float* __restrict__ A,
           const float* __restrict__ W1g,
           const float* __restrict__ b1g,
           const float* __restrict__ W2g,
           const float* __restrict__ b2g,
           float* __restrict__ C) {
    extern __shared__ float sm[];
    float* sA   = sm;
    float* sW1T = sm + 128 * PITCH;
    float* sW2T = sW1T + 128 * PITCH;
    float* sb1  = sW2T + 128 * PITCH;
    float* sb2  = sb1 + 128;

    int tid = threadIdx.x;

    for (int i = tid; i < 128 * 128; i += 512) {
        int k = i >> 7, n = i & 127;
        sW1T[n * PITCH + k] = W1g[i];
        sW2T[n * PITCH + k] = W2g[i];
    }
    if (tid < 128) { sb1[tid] = b1g[tid]; sb2[tid] = b2g[tid]; }

    int lane = tid & 31, wid = tid >> 5;
    int g = lane >> 2, c = lane & 3;
    int wm = wid & 3, wn = wid >> 2;
    int mrow = wm * 32;
    int ncol = wn * 32;

    for (int tile = blockIdx.x; tile < MLP_TILES; tile += gridDim.x) {
        int row0 = tile * 128;

        __syncthreads();
        for (int i = tid; i < 128 * 32; i += 512) {
            int r = i >> 5, k4 = i & 31;
            int gr = row0 + r;
            float4 v = (gr < NN) ? ((const float4*)(A + (size_t)gr * DD))[k4]
                                 : make_float4(0.f, 0.f, 0.f, 0.f);
            *(float4*)(sA + r * PITCH + k4 * 4) = v;
        }
        __syncthreads();

        float acc[2][4][4];
        #pragma unroll
        for (int mt = 0; mt < 2; mt++)
            #pragma unroll
            for (int j = 0; j < 4; j++)
                #pragma unroll
                for (int q = 0; q < 4; q++) acc[mt][j][q] = 0.0f;

        #pragma unroll 1
        for (int s = 0; s < 16; s++) {
            int k0 = s * 8;
            unsigned bhi[4][2], blo[4][2];
            #pragma unroll
            for (int j = 0; j < 4; j++) {
                const float* bp = sW1T + (ncol + 8 * j + g) * PITCH + k0;
                tf32split(bp[c],     bhi[j][0], blo[j][0]);
                tf32split(bp[c + 4], bhi[j][1], blo[j][1]);
            }
            unsigned ahi[2][4], alo[2][4];
            #pragma unroll
            for (int mt = 0; mt < 2; mt++) {
                int r = mrow + mt * 16 + g;
                const float* a0p = sA + r * PITCH + k0;
                const float* a1p = sA + (r + 8) * PITCH + k0;
                tf32split(a0p[c],     ahi[mt][0], alo[mt][0]);
                tf32split(a1p[c],     ahi[mt][1], alo[mt][1]);
                tf32split(a0p[c + 4], ahi[mt][2], alo[mt][2]);
                tf32split(a1p[c + 4], ahi[mt][3], alo[mt][3]);
            }
            #pragma unroll
            for (int mt = 0; mt < 2; mt++)
                #pragma unroll
                for (int j = 0; j < 4; j++) mma_tf32(acc[mt][j], ahi[mt], bhi[j]);
            #pragma unroll
            for (int mt = 0; mt < 2; mt++)
                #pragma unroll
                for (int j = 0; j < 4; j++) mma_tf32(acc[mt][j], ahi[mt], blo[j]);
            #pragma unroll
            for (int mt = 0; mt < 2; mt++)
                #pragma unroll
                for (int j = 0; j < 4; j++) mma_tf32(acc[mt][j], alo[mt], bhi[j]);
        }
        __syncthreads();

        #pragma unroll
        for (int mt = 0; mt < 2; mt++) {
            int r = mrow + mt * 16 + g;
            #pragma unroll
            for (int j = 0; j < 4; j++) {
                int col = ncol + 8 * j + 2 * c;
                float h0 = acc[mt][j][0] + sb1[col];
                float h1 = acc[mt][j][1] + sb1[col + 1];
                float h2 = acc[mt][j][2] + sb1[col];
                float h3 = acc[mt][j][3] + sb1[col + 1];
                h0 = 0.5f * h0 * (1.0f + erff(h0 * 0.70710678118654752f));
                h1 = 0.5f * h1 * (1.0f + erff(h1 * 0.70710678118654752f));
                h2 = 0.5f * h2 * (1.0f + erff(h2 * 0.70710678118654752f));
                h3 = 0.5f * h3 * (1.0f + erff(h3 * 0.70710678118654752f));
                *(float2*)(sA + r * PITCH + col) = make_float2(h0, h1);
                *(float2*)(sA + (r + 8) * PITCH + col) = make_float2(h2, h3);
                acc[mt][j][0] = 0.0f; acc[mt][j][1] = 0.0f;
                acc[mt][j][2] = 0.0f; acc[mt][j][3] = 0.0f;
            }
        }
        __syncthreads();

        #pragma unroll 1
        for (int s = 0; s < 16; s++) {
            int k0 = s * 8;
            unsigned bhi[4][2], blo[4][2];
            #pragma unroll
            for (int j = 0; j < 4; j++) {
                const float* bp = sW2T + (ncol + 8 * j + g) * PITCH + k0;
                tf32split(bp[c],     bhi[j][0], blo[j][0]);
                tf32split(bp[c + 4], bhi[j][1], blo[j][1]);
            }
            unsigned ahi[2][4], alo[2][4];
            #pragma unroll
            for (int mt = 0; mt < 2; mt++) {
                int r = mrow + mt * 16 + g;
                const float* a0p = sA + r * PITCH + k0;
                const float* a1p = sA + (r + 8) * PITCH + k0;
                tf32split(a0p[c],     ahi[mt][0], alo[mt][0]);
                tf32split(a1p[c],     ahi[mt][1], alo[mt][1]);
                tf32split(a0p[c + 4], ahi[mt][2], alo[mt][2]);
                tf32split(a1p[c + 4], ahi[mt][3], alo[mt][3]);
            }
            #pragma unroll
            for (int mt = 0; mt < 2; mt++)
                #pragma unroll
                for (int j = 0; j < 4; j++) mma_tf32(acc[mt][j], ahi[mt], bhi[j]);
            #pragma unroll
            for (int mt = 0; mt < 2; mt++)
                #pragma unroll
                for (int j = 0; j < 4; j++) mma_tf32(acc[mt][j], ahi[mt], blo[j]);
            #pragma unroll
            for (int mt = 0; mt < 2; mt++)
                #pragma unroll
                for (int j = 0; j < 4; j++) mma_tf32(acc[mt][j], alo[mt], bhi[j]);
        }

        #pragma unroll
        for (int mt = 0; mt < 2; mt++) {
            int r = mrow + mt * 16 + g;
            int gr0 = row0 + r, gr1 = row0 + r + 8;
            #pragma unroll
            for (int j = 0; j < 4; j++) {
                int col = ncol + 8 * j + 2 * c;
                if (gr0 < NN)
                    *(float2*)(C + (size_t)gr0 * DD + col) =
                        make_float2(acc[mt][j][0] + sb2[col],
                                    acc[mt][j][1] + sb2[col + 1]);
                if (gr1 < NN)
                    *(float2*)(C + (size_t)gr1 * DD + col) =
                        make_float2(acc[mt][j][2] + sb2[col],
                                    acc[mt][j][3] + sb2[col + 1]);
            }
        }
    }
}

// ---------------------------------------------------------------------------
// Launch
// ---------------------------------------------------------------------------
extern "C" void kernel_launch(void* const* d_in, const int* in_sizes, int n_in,
                              void* d_out, int out_size) {
    const float* x         = (const float*)d_in[0];
    const float* edge_attr = (const float*)d_in[1];
    const float* W1        = (const float*)d_in[2];
    const float* b1        = (const float*)d_in[3];
    const float* W2        = (const float*)d_in[4];
    const float* b2        = (const float*)d_in[5];
    const float* We        = (const float*)d_in[6];
    const float* be        = (const float*)d_in[7];
    const float* eps       = (const float*)d_in[8];
    const void*  edge_idx  = d_in[9];
    float* out = (float*)d_out;

    float *bufA, *bufB;
    cudaGetSymbolAddress((void**)&bufA, g_bufA);
    cudaGetSymbolAddress((void**)&bufB, g_bufB);

    cudaFuncSetAttribute(mlp_kernel,
                         cudaFuncAttributeMaxDynamicSharedMemorySize,
                         MLP_SMEM_BYTES);
    cudaFuncSetAttribute(aggr_tc_kernel,
                         cudaFuncAttributeMaxDynamicSharedMemorySize,
                         AGG_SMEM_BYTES);

    // ---- CSR build + attr pre-sort (once per launch) ----
    detect_idx_kernel<<<1, 32>>>((const long long*)edge_idx);
    zero_cnt_kernel<<<(NN + 255) / 256, 256>>>();
    hist_kernel<<<(NE + 255) / 256, 256>>>(edge_idx);
    local_scan_kernel<<<SCAN_NBLK, 1024>>>();
    scan_sums_kernel<<<1, 64>>>();
    add_off_kernel<<<SCAN_NBLK, 1024>>>();
    scatter_fused_kernel<<<(NE + 255) / 256, 256>>>(edge_idx, edge_attr);

    const float* xin = x;
    for (int l = 0; l < 3; l++) {
        float* aggr = (l == 1) ? bufB : bufA;
        float* xout = (l == 0) ? bufA : ((l == 1) ? bufB : out);

        init_aggr_kernel<<<256, 256>>>(xin, eps, l, aggr);
        aggr_tc_kernel<<<NCHUNK, 256, AGG_SMEM_BYTES>>>(
            xin, We + l * ED * DD, be + l * DD, aggr);
        mlp_kernel<<<148, 512, MLP_SMEM_BYTES>>>(
            aggr, W1 + l * DD * DD, b1 + l * DD,
            W2 + l * DD * DD, b2 + l * DD, xout);
        xin = xout;
    }
}

// round 11
// speedup vs baseline: 1.0993x; 1.0993x over previous
#include <cuda_runtime.h>
#include <math.h>

#define NN 50000
#define NE 800000
#define DD 128
#define ED 16
#define SCAN_NBLK ((NN + 1023) / 1024)   // 49

// Scratch (allocation-free rule: __device__ globals)
__device__ float g_bufA[NN * DD];
__device__ float g_bufB[NN * DD];
__device__ int   g_idx64;
__device__ int   g_cnt[NN];
__device__ int   g_rowptr[NN + 1];
__device__ int   g_cursor[NN];
__device__ int   g_blocksum[SCAN_NBLK];
__device__ int   g_blockoff[SCAN_NBLK];
__device__ int   g_src[NE];              // src node, dst-sorted
__device__ float g_eattr[NE * ED];       // edge_attr rows in dst-sorted order

// ---------------------------------------------------------------------------
// tf32 helpers
// ---------------------------------------------------------------------------
__device__ __forceinline__ void tf32split(float v, unsigned& hi, unsigned& lo) {
    asm("cvt.rna.tf32.f32 %0, %1;" : "=r"(hi) : "f"(v));
    float r = v - __uint_as_float(hi);
    asm("cvt.rna.tf32.f32 %0, %1;" : "=r"(lo) : "f"(r));
}

__device__ __forceinline__ void mma_tf32(float* d, const unsigned* a, const unsigned* b) {
    asm volatile(
        "mma.sync.aligned.m16n8k8.row.col.f32.tf32.tf32.f32 "
        "{%0,%1,%2,%3}, {%4,%5,%6,%7}, {%8,%9}, {%0,%1,%2,%3};"
        : "+f"(d[0]), "+f"(d[1]), "+f"(d[2]), "+f"(d[3])
        : "r"(a[0]), "r"(a[1]), "r"(a[2]), "r"(a[3]), "r"(b[0]), "r"(b[1]));
}

// ---------------------------------------------------------------------------
// Detect int64 vs int32 edge_idx (one warp, ballot)
// ---------------------------------------------------------------------------
__global__ void detect_idx_kernel(const long long* __restrict__ idx) {
    int lane = threadIdx.x;
    long long v = idx[lane];
    int bad = (v < 0 || v >= (long long)NN) ? 1 : 0;
    unsigned m = __ballot_sync(0xffffffffu, bad);
    if (lane == 0) g_idx64 = (m == 0u);
}

// ---------------------------------------------------------------------------
// CSR build
// ---------------------------------------------------------------------------
__global__ void zero_cnt_kernel() {
    int i = blockIdx.x * blockDim.x + threadIdx.x;
    if (i < NN) g_cnt[i] = 0;
}

__global__ void hist_kernel(const void* __restrict__ edge_idx) {
    int e = blockIdx.x * blockDim.x + threadIdx.x;
    if (e >= NE) return;
    int dst;
    if (g_idx64) dst = (int)((const long long*)edge_idx)[NE + e];
    else         dst = ((const int*)edge_idx)[NE + e];
    atomicAdd(&g_cnt[dst], 1);
}

__global__ void local_scan_kernel() {
    __shared__ int sdata[1024];
    int i = blockIdx.x * 1024 + threadIdx.x;
    int v = (i < NN) ? g_cnt[i] : 0;
    sdata[threadIdx.x] = v;
    __syncthreads();
    #pragma unroll
    for (int off = 1; off < 1024; off <<= 1) {
        int t = (threadIdx.x >= off) ? sdata[threadIdx.x - off] : 0;
        __syncthreads();
        sdata[threadIdx.x] += t;
        __syncthreads();
    }
    if (i < NN) g_rowptr[i] = sdata[threadIdx.x] - v;   // local exclusive
    if (threadIdx.x == 1023) g_blocksum[blockIdx.x] = sdata[1023];
}

__global__ void scan_sums_kernel() {
    __shared__ int sd[64];
    int t = threadIdx.x;
    int v = (t < SCAN_NBLK) ? g_blocksum[t] : 0;
    sd[t] = v;
    __syncthreads();
    #pragma unroll
    for (int off = 1; off < 64; off <<= 1) {
        int u = (t >= off) ? sd[t - off] : 0;
        __syncthreads();
        sd[t] += u;
        __syncthreads();
    }
    if (t < SCAN_NBLK) g_blockoff[t] = sd[t] - v;   // exclusive
}

__global__ void add_off_kernel() {
    int i = blockIdx.x * 1024 + threadIdx.x;
    if (i < NN) {
        int v = g_rowptr[i] + g_blockoff[blockIdx.x];
        g_rowptr[i] = v;
        g_cursor[i] = v;
    }
    if (i == 0) g_rowptr[NN] = NE;
}

// Fused scatter: place src AND the edge_attr row directly into dst-sorted order.
__global__ void scatter_fused_kernel(const void* __restrict__ edge_idx,
                                     const float* __restrict__ edge_attr) {
    int e = blockIdx.x * blockDim.x + threadIdx.x;
    if (e >= NE) return;
    int src, dst;
    if (g_idx64) {
        src = (int)((const long long*)edge_idx)[e];
        dst = (int)((const long long*)edge_idx)[NE + e];
    } else {
        src = ((const int*)edge_idx)[e];
        dst = ((const int*)edge_idx)[NE + e];
    }
    const float4* ea = (const float4*)(edge_attr + (size_t)e * ED);
    float4 a0 = ea[0], a1 = ea[1], a2 = ea[2], a3 = ea[3];
    int pos = atomicAdd(&g_cursor[dst], 1);
    g_src[pos] = src;
    float4* dstp = (float4*)(g_eattr + (size_t)pos * ED);
    dstp[0] = a0; dstp[1] = a1; dstp[2] = a2; dstp[3] = a3;
}

// ---------------------------------------------------------------------------
// Edge aggregation (CSR, no atomics): TWO warps per dst node, each owning 64
// feature cols (float2 per lane). We tile = 32 regs/lane -> ~90-100 regs total
// -> 2 blocks/SM (4 warps/SMSP) for latency hiding. Edge loop unrolled by 2.
// ---------------------------------------------------------------------------
#define MC2(m, t0, t1, t2, t3)                          \
    m.x += t0.x*w[0].x;  m.y += t0.x*w[0].y;            \
    m.x += t0.y*w[1].x;  m.y += t0.y*w[1].y;            \
    m.x += t0.z*w[2].x;  m.y += t0.z*w[2].y;            \
    m.x += t0.w*w[3].x;  m.y += t0.w*w[3].y;            \
    m.x += t1.x*w[4].x;  m.y += t1.x*w[4].y;            \
    m.x += t1.y*w[5].x;  m.y += t1.y*w[5].y;            \
    m.x += t1.z*w[6].x;  m.y += t1.z*w[6].y;            \
    m.x += t1.w*w[7].x;  m.y += t1.w*w[7].y;            \
    m.x += t2.x*w[8].x;  m.y += t2.x*w[8].y;            \
    m.x += t2.y*w[9].x;  m.y += t2.y*w[9].y;            \
    m.x += t2.z*w[10].x; m.y += t2.z*w[10].y;           \
    m.x += t2.w*w[11].x; m.y += t2.w*w[11].y;           \
    m.x += t3.x*w[12].x; m.y += t3.x*w[12].y;           \
    m.x += t3.y*w[13].x; m.y += t3.y*w[13].y;           \
    m.x += t3.z*w[14].x; m.y += t3.z*w[14].y;           \
    m.x += t3.w*w[15].x; m.y += t3.w*w[15].y;

__global__ void __launch_bounds__(256, 2)
aggr_kernel(const float* __restrict__ xin,
            const float* __restrict__ We,
            const float* __restrict__ be,
            const float* __restrict__ eps, int l,
            float* __restrict__ aggr) {
    int lane = threadIdx.x & 31;
    int gw = (blockIdx.x * blockDim.x + threadIdx.x) >> 5;  // global warp
    int d = gw >> 1;                     // node (grid sized exactly: 2*NN warps)
    int c0 = (gw & 1) * 64 + lane * 2;   // this warp's 64-col half

    float2 w[ED];
    #pragma unroll
    for (int k = 0; k < ED; k++)
        w[k] = *(const float2*)(We + k * DD + c0);
    float2 bias = *(const float2*)(be + c0);
    float s = 1.0f + eps[l];

    float2 xv = *(const float2*)(xin + (size_t)d * DD + c0);
    float2 acc = make_float2(xv.x * s, xv.y * s);
    int beg = g_rowptr[d], end = g_rowptr[d + 1];

    int j = beg;
    for (; j + 1 < end; j += 2) {
        int s0 = g_src[j];
        int s1 = g_src[j + 1];
        const float4* p0 = (const float4*)(g_eattr + (size_t)j * ED);
        float4 a0 = p0[0], a1 = p0[1], a2 = p0[2], a3 = p0[3];
        float4 b0 = p0[4], b1 = p0[5], b2 = p0[6], b3 = p0[7];
        float2 xs0 = *(const float2*)(xin + (size_t)s0 * DD + c0);
        float2 xs1 = *(const float2*)(xin + (size_t)s1 * DD + c0);

        float2 m0 = bias;
        MC2(m0, a0, a1, a2, a3)
        float2 m1 = bias;
        MC2(m1, b0, b1, b2, b3)

        acc.x += fmaxf(m0.x + xs0.x, 0.0f) + fmaxf(m1.x + xs1.x, 0.0f);
        acc.y += fmaxf(m0.y + xs0.y, 0.0f) + fmaxf(m1.y + xs1.y, 0.0f);
    }
    if (j < end) {
        int s0 = g_src[j];
        const float4* p0 = (const float4*)(g_eattr + (size_t)j * ED);
        float4 a0 = p0[0], a1 = p0[1], a2 = p0[2], a3 = p0[3];
        float2 xs0 = *(const float2*)(xin + (size_t)s0 * DD + c0);
        float2 m0 = bias;
        MC2(m0, a0, a1, a2, a3)
        acc.x += fmaxf(m0.x + xs0.x, 0.0f);
        acc.y += fmaxf(m0.y + xs0.y, 0.0f);
    }
    *(float2*)(aggr + (size_t)d * DD + c0) = acc;
}

// ---------------------------------------------------------------------------
// Fused node MLP with tf32 tensor cores (3-way split) — unchanged from R9.
// Persistent, grid=148, 512 threads (16 warps, 4x4 warp grid).
// ---------------------------------------------------------------------------
#define PITCH 132
#define MLP_TILES ((NN + 127) / 128)     // 391
#define MLP_SMEM_FLOATS (3 * 128 * PITCH + 256)
#define MLP_SMEM_BYTES (MLP_SMEM_FLOATS * 4)

__global__ void __launch_bounds__(512)
mlp_kernel(const float* __restrict__ A,
           const float* __restrict__ W1g,
           const float* __restrict__ b1g,
           const float* __restrict__ W2g,
           const float* __restrict__ b2g,
           float* __restrict__ C) {
    extern __shared__ float sm[];
    float* sA   = sm;
    float* sW1T = sm + 128 * PITCH;
    float* sW2T = sW1T + 128 * PITCH;
    float* sb1  = sW2T + 128 * PITCH;
    float* sb2  = sb1 + 128;

    int tid = threadIdx.x;

    for (int i = tid; i < 128 * 128; i += 512) {
        int k = i >> 7, n = i & 127;
        sW1T[n * PITCH + k] = W1g[i];
        sW2T[n * PITCH + k] = W2g[i];
    }
    if (tid < 128) { sb1[tid] = b1g[tid]; sb2[tid] = b2g[tid]; }

    int lane = tid & 31, wid = tid >> 5;
    int g = lane >> 2, c = lane & 3;
    int wm = wid & 3, wn = wid >> 2;
    int mrow = wm * 32;
    int ncol = wn * 32;

    for (int tile = blockIdx.x; tile < MLP_TILES; tile += gridDim.x) {
        int row0 = tile * 128;

        __syncthreads();
        for (int i = tid; i < 128 * 32; i += 512) {
            int r = i >> 5, k4 = i & 31;
            int gr = row0 + r;
            float4 v = (gr < NN) ? ((const float4*)(A + (size_t)gr * DD))[k4]
                                 : make_float4(0.f, 0.f, 0.f, 0.f);
            *(float4*)(sA + r * PITCH + k4 * 4) = v;
        }
        __syncthreads();

        float acc[2][4][4];
        #pragma unroll
        for (int mt = 0; mt < 2; mt++)
            #pragma unroll
            for (int j = 0; j < 4; j++)
                #pragma unroll
                for (int q = 0; q < 4; q++) acc[mt][j][q] = 0.0f;

        #pragma unroll 1
        for (int s = 0; s < 16; s++) {
            int k0 = s * 8;
            unsigned bhi[4][2], blo[4][2];
            #pragma unroll
            for (int j = 0; j < 4; j++) {
                const float* bp = sW1T + (ncol + 8 * j + g) * PITCH + k0;
                tf32split(bp[c],     bhi[j][0], blo[j][0]);
                tf32split(bp[c + 4], bhi[j][1], blo[j][1]);
            }
            unsigned ahi[2][4], alo[2][4];
            #pragma unroll
            for (int mt = 0; mt < 2; mt++) {
                int r = mrow + mt * 16 + g;
                const float* a0p = sA + r * PITCH + k0;
                const float* a1p = sA + (r + 8) * PITCH + k0;
                tf32split(a0p[c],     ahi[mt][0], alo[mt][0]);
                tf32split(a1p[c],     ahi[mt][1], alo[mt][1]);
                tf32split(a0p[c + 4], ahi[mt][2], alo[mt][2]);
                tf32split(a1p[c + 4], ahi[mt][3], alo[mt][3]);
            }
            #pragma unroll
            for (int mt = 0; mt < 2; mt++)
                #pragma unroll
                for (int j = 0; j < 4; j++) mma_tf32(acc[mt][j], ahi[mt], bhi[j]);
            #pragma unroll
            for (int mt = 0; mt < 2; mt++)
                #pragma unroll
                for (int j = 0; j < 4; j++) mma_tf32(acc[mt][j], ahi[mt], blo[j]);
            #pragma unroll
            for (int mt = 0; mt < 2; mt++)
                #pragma unroll
                for (int j = 0; j < 4; j++) mma_tf32(acc[mt][j], alo[mt], bhi[j]);
        }
        __syncthreads();

        #pragma unroll
        for (int mt = 0; mt < 2; mt++) {
            int r = mrow + mt * 16 + g;
            #pragma unroll
            for (int j = 0; j < 4; j++) {
                int col = ncol + 8 * j + 2 * c;
                float h0 = acc[mt][j][0] + sb1[col];
                float h1 = acc[mt][j][1] + sb1[col + 1];
                float h2 = acc[mt][j][2] + sb1[col];
                float h3 = acc[mt][j][3] + sb1[col + 1];
                h0 = 0.5f * h0 * (1.0f + erff(h0 * 0.70710678118654752f));
                h1 = 0.5f * h1 * (1.0f + erff(h1 * 0.70710678118654752f));
                h2 = 0.5f * h2 * (1.0f + erff(h2 * 0.70710678118654752f));
                h3 = 0.5f * h3 * (1.0f + erff(h3 * 0.70710678118654752f));
                *(float2*)(sA + r * PITCH + col) = make_float2(h0, h1);
                *(float2*)(sA + (r + 8) * PITCH + col) = make_float2(h2, h3);
                acc[mt][j][0] = 0.0f; acc[mt][j][1] = 0.0f;
                acc[mt][j][2] = 0.0f; acc[mt][j][3] = 0.0f;
            }
        }
        __syncthreads();

        #pragma unroll 1
        for (int s = 0; s < 16; s++) {
            int k0 = s * 8;
            unsigned bhi[4][2], blo[4][2];
            #pragma unroll
            for (int j = 0; j < 4; j++) {
                const float* bp = sW2T + (ncol + 8 * j + g) * PITCH + k0;
                tf32split(bp[c],     bhi[j][0], blo[j][0]);
                tf32split(bp[c + 4], bhi[j][1], blo[j][1]);
            }
            unsigned ahi[2][4], alo[2][4];
            #pragma unroll
            for (int mt = 0; mt < 2; mt++) {
                int r = mrow + mt * 16 + g;
                const float* a0p = sA + r * PITCH + k0;
                const float* a1p = sA + (r + 8) * PITCH + k0;
                tf32split(a0p[c],     ahi[mt][0], alo[mt][0]);
                tf32split(a1p[c],     ahi[mt][1], alo[mt][1]);
                tf32split(a0p[c + 4], ahi[mt][2], alo[mt][2]);
                tf32split(a1p[c + 4], ahi[mt][3], alo[mt][3]);
            }
            #pragma unroll
            for (int mt = 0; mt < 2; mt++)
                #pragma unroll
                for (int j = 0; j < 4; j++) mma_tf32(acc[mt][j], ahi[mt], bhi[j]);
            #pragma unroll
            for (int mt = 0; mt < 2; mt++)
                #pragma unroll
                for (int j = 0; j < 4; j++) mma_tf32(acc[mt][j], ahi[mt], blo[j]);
            #pragma unroll
            for (int mt = 0; mt < 2; mt++)
                #pragma unroll
                for (int j = 0; j < 4; j++) mma_tf32(acc[mt][j], alo[mt], bhi[j]);
        }

        #pragma unroll
        for (int mt = 0; mt < 2; mt++) {
            int r = mrow + mt * 16 + g;
            int gr0 = row0 + r, gr1 = row0 + r + 8;
            #pragma unroll
            for (int j = 0; j < 4; j++) {
                int col = ncol + 8 * j + 2 * c;
                if (gr0 < NN)
                    *(float2*)(C + (size_t)gr0 * DD + col) =
                        make_float2(acc[mt][j][0] + sb2[col],
                                    acc[mt][j][1] + sb2[col + 1]);
                if (gr1 < NN)
                    *(float2*)(C + (size_t)gr1 * DD + col) =
                        make_float2(acc[mt][j][2] + sb2[col],
                                    acc[mt][j][3] + sb2[col + 1]);
            }
        }
    }
}

// ---------------------------------------------------------------------------
// Launch
// ---------------------------------------------------------------------------
extern "C" void kernel_launch(void* const* d_in, const int* in_sizes, int n_in,
                              void* d_out, int out_size) {
    const float* x         = (const float*)d_in[0];
    const float* edge_attr = (const float*)d_in[1];
    const float* W1        = (const float*)d_in[2];
    const float* b1        = (const float*)d_in[3];
    const float* W2        = (const float*)d_in[4];
    const float* b2        = (const float*)d_in[5];
    const float* We        = (const float*)d_in[6];
    const float* be        = (const float*)d_in[7];
    const float* eps       = (const float*)d_in[8];
    const void*  edge_idx  = d_in[9];
    float* out = (float*)d_out;

    float *bufA, *bufB;
    cudaGetSymbolAddress((void**)&bufA, g_bufA);
    cudaGetSymbolAddress((void**)&bufB, g_bufB);

    cudaFuncSetAttribute(mlp_kernel,
                         cudaFuncAttributeMaxDynamicSharedMemorySize,
                         MLP_SMEM_BYTES);

    // ---- CSR build + attr pre-sort (once per launch) ----
    detect_idx_kernel<<<1, 32>>>((const long long*)edge_idx);
    zero_cnt_kernel<<<(NN + 255) / 256, 256>>>();
    hist_kernel<<<(NE + 255) / 256, 256>>>(edge_idx);
    local_scan_kernel<<<SCAN_NBLK, 1024>>>();
    scan_sums_kernel<<<1, 64>>>();
    add_off_kernel<<<SCAN_NBLK, 1024>>>();
    scatter_fused_kernel<<<(NE + 255) / 256, 256>>>(edge_idx, edge_attr);

    const int aggr_blocks = (NN * 2 * 32) / 256;   // 12500: two warps per node

    const float* xin = x;
    for (int l = 0; l < 3; l++) {
        float* aggr = (l == 1) ? bufB : bufA;
        float* xout = (l == 0) ? bufA : ((l == 1) ? bufB : out);

        aggr_kernel<<<aggr_blocks, 256>>>(xin, We + l * ED * DD,
                                          be + l * DD, eps, l, aggr);
        mlp_kernel<<<148, 512, MLP_SMEM_BYTES>>>(
            aggr, W1 + l * DD * DD, b1 + l * DD,
            W2 + l * DD * DD, b2 + l * DD, xout);
        xin = xout;
    }
}

// round 12
// speedup vs baseline: 1.3713x; 1.2474x over previous
#include <cuda_runtime.h>
#include <math.h>

#define NN 50000
#define NE 800000
#define DD 128
#define ED 16
#define SCAN_NBLK ((NN + 1023) / 1024)   // 49

// Scratch (allocation-free rule: __device__ globals)
__device__ float g_bufA[NN * DD];
__device__ float g_bufB[NN * DD];
__device__ int   g_idx64;
__device__ int   g_cnt[NN];
__device__ int   g_rowptr[NN + 1];
__device__ int   g_cursor[NN];
__device__ int   g_blocksum[SCAN_NBLK];
__device__ int   g_blockoff[SCAN_NBLK];
__device__ int   g_src[NE];              // src node, dst-sorted
__device__ float g_eattr[NE * ED];       // edge_attr rows in dst-sorted order

// ---------------------------------------------------------------------------
// tf32 helpers
// ---------------------------------------------------------------------------
__device__ __forceinline__ void tf32split(float v, unsigned& hi, unsigned& lo) {
    asm("cvt.rna.tf32.f32 %0, %1;" : "=r"(hi) : "f"(v));
    float r = v - __uint_as_float(hi);
    asm("cvt.rna.tf32.f32 %0, %1;" : "=r"(lo) : "f"(r));
}

__device__ __forceinline__ void mma_tf32(float* d, const unsigned* a, const unsigned* b) {
    asm volatile(
        "mma.sync.aligned.m16n8k8.row.col.f32.tf32.tf32.f32 "
        "{%0,%1,%2,%3}, {%4,%5,%6,%7}, {%8,%9}, {%0,%1,%2,%3};"
        : "+f"(d[0]), "+f"(d[1]), "+f"(d[2]), "+f"(d[3])
        : "r"(a[0]), "r"(a[1]), "r"(a[2]), "r"(a[3]), "r"(b[0]), "r"(b[1]));
}

// ---------------------------------------------------------------------------
// Detect int64 vs int32 edge_idx (one warp, ballot)
// ---------------------------------------------------------------------------
__global__ void detect_idx_kernel(const long long* __restrict__ idx) {
    int lane = threadIdx.x;
    long long v = idx[lane];
    int bad = (v < 0 || v >= (long long)NN) ? 1 : 0;
    unsigned m = __ballot_sync(0xffffffffu, bad);
    if (lane == 0) g_idx64 = (m == 0u);
}

// ---------------------------------------------------------------------------
// CSR build
// ---------------------------------------------------------------------------
__global__ void zero_cnt_kernel() {
    int i = blockIdx.x * blockDim.x + threadIdx.x;
    if (i < NN) g_cnt[i] = 0;
}

__global__ void hist_kernel(const void* __restrict__ edge_idx) {
    int e = blockIdx.x * blockDim.x + threadIdx.x;
    if (e >= NE) return;
    int dst;
    if (g_idx64) dst = (int)((const long long*)edge_idx)[NE + e];
    else         dst = ((const int*)edge_idx)[NE + e];
    atomicAdd(&g_cnt[dst], 1);
}

__global__ void local_scan_kernel() {
    __shared__ int sdata[1024];
    int i = blockIdx.x * 1024 + threadIdx.x;
    int v = (i < NN) ? g_cnt[i] : 0;
    sdata[threadIdx.x] = v;
    __syncthreads();
    #pragma unroll
    for (int off = 1; off < 1024; off <<= 1) {
        int t = (threadIdx.x >= off) ? sdata[threadIdx.x - off] : 0;
        __syncthreads();
        sdata[threadIdx.x] += t;
        __syncthreads();
    }
    if (i < NN) g_rowptr[i] = sdata[threadIdx.x] - v;   // local exclusive
    if (threadIdx.x == 1023) g_blocksum[blockIdx.x] = sdata[1023];
}

__global__ void scan_sums_kernel() {
    __shared__ int sd[64];
    int t = threadIdx.x;
    int v = (t < SCAN_NBLK) ? g_blocksum[t] : 0;
    sd[t] = v;
    __syncthreads();
    #pragma unroll
    for (int off = 1; off < 64; off <<= 1) {
        int u = (t >= off) ? sd[t - off] : 0;
        __syncthreads();
        sd[t] += u;
        __syncthreads();
    }
    if (t < SCAN_NBLK) g_blockoff[t] = sd[t] - v;   // exclusive
}

__global__ void add_off_kernel() {
    int i = blockIdx.x * 1024 + threadIdx.x;
    if (i < NN) {
        int v = g_rowptr[i] + g_blockoff[blockIdx.x];
        g_rowptr[i] = v;
        g_cursor[i] = v;
    }
    if (i == 0) g_rowptr[NN] = NE;
}

// Fused scatter: place src AND the edge_attr row directly into dst-sorted order.
__global__ void scatter_fused_kernel(const void* __restrict__ edge_idx,
                                     const float* __restrict__ edge_attr) {
    int e = blockIdx.x * blockDim.x + threadIdx.x;
    if (e >= NE) return;
    int src, dst;
    if (g_idx64) {
        src = (int)((const long long*)edge_idx)[e];
        dst = (int)((const long long*)edge_idx)[NE + e];
    } else {
        src = ((const int*)edge_idx)[e];
        dst = ((const int*)edge_idx)[NE + e];
    }
    const float4* ea = (const float4*)(edge_attr + (size_t)e * ED);
    float4 a0 = ea[0], a1 = ea[1], a2 = ea[2], a3 = ea[3];
    int pos = atomicAdd(&g_cursor[dst], 1);
    g_src[pos] = src;
    float4* dstp = (float4*)(g_eattr + (size_t)pos * ED);
    dstp[0] = a0; dstp[1] = a1; dstp[2] = a2; dstp[3] = a3;
}

// ---------------------------------------------------------------------------
// Edge aggregation (CSR, no atomics): one warp per dst node (R9 body).
// 128-thread blocks -> 3 blocks/SM (3 warps/SMSP) at ~130 regs, same traffic.
// ---------------------------------------------------------------------------
#define MCHAIN(m, t0, t1, t2, t3)                                              \
    m.x += t0.x*w[0].x;  m.y += t0.x*w[0].y;  m.z += t0.x*w[0].z;  m.w += t0.x*w[0].w;  \
    m.x += t0.y*w[1].x;  m.y += t0.y*w[1].y;  m.z += t0.y*w[1].z;  m.w += t0.y*w[1].w;  \
    m.x += t0.z*w[2].x;  m.y += t0.z*w[2].y;  m.z += t0.z*w[2].z;  m.w += t0.z*w[2].w;  \
    m.x += t0.w*w[3].x;  m.y += t0.w*w[3].y;  m.z += t0.w*w[3].z;  m.w += t0.w*w[3].w;  \
    m.x += t1.x*w[4].x;  m.y += t1.x*w[4].y;  m.z += t1.x*w[4].z;  m.w += t1.x*w[4].w;  \
    m.x += t1.y*w[5].x;  m.y += t1.y*w[5].y;  m.z += t1.y*w[5].z;  m.w += t1.y*w[5].w;  \
    m.x += t1.z*w[6].x;  m.y += t1.z*w[6].y;  m.z += t1.z*w[6].z;  m.w += t1.z*w[6].w;  \
    m.x += t1.w*w[7].x;  m.y += t1.w*w[7].y;  m.z += t1.w*w[7].z;  m.w += t1.w*w[7].w;  \
    m.x += t2.x*w[8].x;  m.y += t2.x*w[8].y;  m.z += t2.x*w[8].z;  m.w += t2.x*w[8].w;  \
    m.x += t2.y*w[9].x;  m.y += t2.y*w[9].y;  m.z += t2.y*w[9].z;  m.w += t2.y*w[9].w;  \
    m.x += t2.z*w[10].x; m.y += t2.z*w[10].y; m.z += t2.z*w[10].z; m.w += t2.z*w[10].w; \
    m.x += t2.w*w[11].x; m.y += t2.w*w[11].y; m.z += t2.w*w[11].z; m.w += t2.w*w[11].w; \
    m.x += t3.x*w[12].x; m.y += t3.x*w[12].y; m.z += t3.x*w[12].z; m.w += t3.x*w[12].w; \
    m.x += t3.y*w[13].x; m.y += t3.y*w[13].y; m.z += t3.y*w[13].z; m.w += t3.y*w[13].w; \
    m.x += t3.z*w[14].x; m.y += t3.z*w[14].y; m.z += t3.z*w[14].z; m.w += t3.z*w[14].w; \
    m.x += t3.w*w[15].x; m.y += t3.w*w[15].y; m.z += t3.w*w[15].z; m.w += t3.w*w[15].w;

__global__ void __launch_bounds__(128)
aggr_kernel(const float* __restrict__ xin,
            const float* __restrict__ We,
            const float* __restrict__ be,
            const float* __restrict__ eps, int l,
            float* __restrict__ aggr) {
    int lane = threadIdx.x & 31;
    int warp = (blockIdx.x * blockDim.x + threadIdx.x) >> 5;
    int nwarps = (gridDim.x * blockDim.x) >> 5;
    int c0 = lane * 4;

    float4 w[ED];
    #pragma unroll
    for (int k = 0; k < ED; k++)
        w[k] = *(const float4*)(We + k * DD + c0);
    float4 bias = *(const float4*)(be + c0);
    float s = 1.0f + eps[l];

    for (int d = warp; d < NN; d += nwarps) {
        float4 xv = *(const float4*)(xin + (size_t)d * DD + c0);
        float4 acc = make_float4(xv.x * s, xv.y * s, xv.z * s, xv.w * s);
        int beg = g_rowptr[d], end = g_rowptr[d + 1];

        int j = beg;
        for (; j + 1 < end; j += 2) {
            int s0 = g_src[j];
            int s1 = g_src[j + 1];
            const float4* p0 = (const float4*)(g_eattr + (size_t)j * ED);
            float4 a0 = p0[0], a1 = p0[1], a2 = p0[2], a3 = p0[3];
            float4 b0 = p0[4], b1 = p0[5], b2 = p0[6], b3 = p0[7];
            float4 xs0 = *(const float4*)(xin + (size_t)s0 * DD + c0);
            float4 xs1 = *(const float4*)(xin + (size_t)s1 * DD + c0);

            float4 m0 = bias;
            MCHAIN(m0, a0, a1, a2, a3)
            float4 m1 = bias;
            MCHAIN(m1, b0, b1, b2, b3)

            acc.x += fmaxf(m0.x + xs0.x, 0.0f) + fmaxf(m1.x + xs1.x, 0.0f);
            acc.y += fmaxf(m0.y + xs0.y, 0.0f) + fmaxf(m1.y + xs1.y, 0.0f);
            acc.z += fmaxf(m0.z + xs0.z, 0.0f) + fmaxf(m1.z + xs1.z, 0.0f);
            acc.w += fmaxf(m0.w + xs0.w, 0.0f) + fmaxf(m1.w + xs1.w, 0.0f);
        }
        if (j < end) {
            int s0 = g_src[j];
            const float4* p0 = (const float4*)(g_eattr + (size_t)j * ED);
            float4 a0 = p0[0], a1 = p0[1], a2 = p0[2], a3 = p0[3];
            float4 xs0 = *(const float4*)(xin + (size_t)s0 * DD + c0);
            float4 m0 = bias;
            MCHAIN(m0, a0, a1, a2, a3)
            acc.x += fmaxf(m0.x + xs0.x, 0.0f);
            acc.y += fmaxf(m0.y + xs0.y, 0.0f);
            acc.z += fmaxf(m0.z + xs0.z, 0.0f);
            acc.w += fmaxf(m0.w + xs0.w, 0.0f);
        }
        *(float4*)(aggr + (size_t)d * DD + c0) = acc;
    }
}

// ---------------------------------------------------------------------------
// Fused node MLP with tf32 tensor cores (3-way split) — unchanged from R9.
// Persistent, grid=148, 512 threads (16 warps, 4x4 warp grid).
// ---------------------------------------------------------------------------
#define PITCH 132
#define MLP_TILES ((NN + 127) / 128)     // 391
#define MLP_SMEM_FLOATS (3 * 128 * PITCH + 256)
#define MLP_SMEM_BYTES (MLP_SMEM_FLOATS * 4)

__global__ void __launch_bounds__(512)
mlp_kernel(const float* __restrict__ A,
           const float* __restrict__ W1g,
           const float* __restrict__ b1g,
           const float* __restrict__ W2g,
           const float* __restrict__ b2g,
           float* __restrict__ C) {
    extern __shared__ float sm[];
    float* sA   = sm;
    float* sW1T = sm + 128 * PITCH;
    float* sW2T = sW1T + 128 * PITCH;
    float* sb1  = sW2T + 128 * PITCH;
    float* sb2  = sb1 + 128;

    int tid = threadIdx.x;

    for (int i = tid; i < 128 * 128; i += 512) {
        int k = i >> 7, n = i & 127;
        sW1T[n * PITCH + k] = W1g[i];
        sW2T[n * PITCH + k] = W2g[i];
    }
    if (tid < 128) { sb1[tid] = b1g[tid]; sb2[tid] = b2g[tid]; }

    int lane = tid & 31, wid = tid >> 5;
    int g = lane >> 2, c = lane & 3;
    int wm = wid & 3, wn = wid >> 2;
    int mrow = wm * 32;
    int ncol = wn * 32;

    for (int tile = blockIdx.x; tile < MLP_TILES; tile += gridDim.x) {
        int row0 = tile * 128;

        __syncthreads();
        for (int i = tid; i < 128 * 32; i += 512) {
            int r = i >> 5, k4 = i & 31;
            int gr = row0 + r;
            float4 v = (gr < NN) ? ((const float4*)(A + (size_t)gr * DD))[k4]
                                 : make_float4(0.f, 0.f, 0.f, 0.f);
            *(float4*)(sA + r * PITCH + k4 * 4) = v;
        }
        __syncthreads();

        float acc[2][4][4];
        #pragma unroll
        for (int mt = 0; mt < 2; mt++)
            #pragma unroll
            for (int j = 0; j < 4; j++)
                #pragma unroll
                for (int q = 0; q < 4; q++) acc[mt][j][q] = 0.0f;

        #pragma unroll 1
        for (int s = 0; s < 16; s++) {
            int k0 = s * 8;
            unsigned bhi[4][2], blo[4][2];
            #pragma unroll
            for (int j = 0; j < 4; j++) {
                const float* bp = sW1T + (ncol + 8 * j + g) * PITCH + k0;
                tf32split(bp[c],     bhi[j][0], blo[j][0]);
                tf32split(bp[c + 4], bhi[j][1], blo[j][1]);
            }
            unsigned ahi[2][4], alo[2][4];
            #pragma unroll
            for (int mt = 0; mt < 2; mt++) {
                int r = mrow + mt * 16 + g;
                const float* a0p = sA + r * PITCH + k0;
                const float* a1p = sA + (r + 8) * PITCH + k0;
                tf32split(a0p[c],     ahi[mt][0], alo[mt][0]);
                tf32split(a1p[c],     ahi[mt][1], alo[mt][1]);
                tf32split(a0p[c + 4], ahi[mt][2], alo[mt][2]);
                tf32split(a1p[c + 4], ahi[mt][3], alo[mt][3]);
            }
            #pragma unroll
            for (int mt = 0; mt < 2; mt++)
                #pragma unroll
                for (int j = 0; j < 4; j++) mma_tf32(acc[mt][j], ahi[mt], bhi[j]);
            #pragma unroll
            for (int mt = 0; mt < 2; mt++)
                #pragma unroll
                for (int j = 0; j < 4; j++) mma_tf32(acc[mt][j], ahi[mt], blo[j]);
            #pragma unroll
            for (int mt = 0; mt < 2; mt++)
                #pragma unroll
                for (int j = 0; j < 4; j++) mma_tf32(acc[mt][j], alo[mt], bhi[j]);
        }
        __syncthreads();

        #pragma unroll
        for (int mt = 0; mt < 2; mt++) {
            int r = mrow + mt * 16 + g;
            #pragma unroll
            for (int j = 0; j < 4; j++) {
                int col = ncol + 8 * j + 2 * c;
                float h0 = acc[mt][j][0] + sb1[col];
                float h1 = acc[mt][j][1] + sb1[col + 1];
                float h2 = acc[mt][j][2] + sb1[col];
                float h3 = acc[mt][j][3] + sb1[col + 1];
                h0 = 0.5f * h0 * (1.0f + erff(h0 * 0.70710678118654752f));
                h1 = 0.5f * h1 * (1.0f + erff(h1 * 0.70710678118654752f));
                h2 = 0.5f * h2 * (1.0f + erff(h2 * 0.70710678118654752f));
                h3 = 0.5f * h3 * (1.0f + erff(h3 * 0.70710678118654752f));
                *(float2*)(sA + r * PITCH + col) = make_float2(h0, h1);
                *(float2*)(sA + (r + 8) * PITCH + col) = make_float2(h2, h3);
                acc[mt][j][0] = 0.0f; acc[mt][j][1] = 0.0f;
                acc[mt][j][2] = 0.0f; acc[mt][j][3] = 0.0f;
            }
        }
        __syncthreads();

        #pragma unroll 1
        for (int s = 0; s < 16; s++) {
            int k0 = s * 8;
            unsigned bhi[4][2], blo[4][2];
            #pragma unroll
            for (int j = 0; j < 4; j++) {
                const float* bp = sW2T + (ncol + 8 * j + g) * PITCH + k0;
                tf32split(bp[c],     bhi[j][0], blo[j][0]);
                tf32split(bp[c + 4], bhi[j][1], blo[j][1]);
            }
            unsigned ahi[2][4], alo[2][4];
            #pragma unroll
            for (int mt = 0; mt < 2; mt++) {
                int r = mrow + mt * 16 + g;
                const float* a0p = sA + r * PITCH + k0;
                const float* a1p = sA + (r + 8) * PITCH + k0;
                tf32split(a0p[c],     ahi[mt][0], alo[mt][0]);
                tf32split(a1p[c],     ahi[mt][1], alo[mt][1]);
                tf32split(a0p[c + 4], ahi[mt][2], alo[mt][2]);
                tf32split(a1p[c + 4], ahi[mt][3], alo[mt][3]);
            }
            #pragma unroll
            for (int mt = 0; mt < 2; mt++)
                #pragma unroll
                for (int j = 0; j < 4; j++) mma_tf32(acc[mt][j], ahi[mt], bhi[j]);
            #pragma unroll
            for (int mt = 0; mt < 2; mt++)
                #pragma unroll
                for (int j = 0; j < 4; j++) mma_tf32(acc[mt][j], ahi[mt], blo[j]);
            #pragma unroll
            for (int mt = 0; mt < 2; mt++)
                #pragma unroll
                for (int j = 0; j < 4; j++) mma_tf32(acc[mt][j], alo[mt], bhi[j]);
        }

        #pragma unroll
        for (int mt = 0; mt < 2; mt++) {
            int r = mrow + mt * 16 + g;
            int gr0 = row0 + r, gr1 = row0 + r + 8;
            #pragma unroll
            for (int j = 0; j < 4; j++) {
                int col = ncol + 8 * j + 2 * c;
                if (gr0 < NN)
                    *(float2*)(C + (size_t)gr0 * DD + col) =
                        make_float2(acc[mt][j][0] + sb2[col],
                                    acc[mt][j][1] + sb2[col + 1]);
                if (gr1 < NN)
                    *(float2*)(C + (size_t)gr1 * DD + col) =
                        make_float2(acc[mt][j][2] + sb2[col],
                                    acc[mt][j][3] + sb2[col + 1]);
            }
        }
    }
}

// ---------------------------------------------------------------------------
// Launch
// ---------------------------------------------------------------------------
extern "C" void kernel_launch(void* const* d_in, const int* in_sizes, int n_in,
                              void* d_out, int out_size) {
    const float* x         = (const float*)d_in[0];
    const float* edge_attr = (const float*)d_in[1];
    const float* W1        = (const float*)d_in[2];
    const float* b1        = (const float*)d_in[3];
    const float* W2        = (const float*)d_in[4];
    const float* b2        = (const float*)d_in[5];
    const float* We        = (const float*)d_in[6];
    const float* be        = (const float*)d_in[7];
    const float* eps       = (const float*)d_in[8];
    const void*  edge_idx  = d_in[9];
    float* out = (float*)d_out;

    float *bufA, *bufB;
    cudaGetSymbolAddress((void**)&bufA, g_bufA);
    cudaGetSymbolAddress((void**)&bufB, g_bufB);

    cudaFuncSetAttribute(mlp_kernel,
                         cudaFuncAttributeMaxDynamicSharedMemorySize,
                         MLP_SMEM_BYTES);

    // ---- CSR build + attr pre-sort (once per launch) ----
    detect_idx_kernel<<<1, 32>>>((const long long*)edge_idx);
    zero_cnt_kernel<<<(NN + 255) / 256, 256>>>();
    hist_kernel<<<(NE + 255) / 256, 256>>>(edge_idx);
    local_scan_kernel<<<SCAN_NBLK, 1024>>>();
    scan_sums_kernel<<<1, 64>>>();
    add_off_kernel<<<SCAN_NBLK, 1024>>>();
    scatter_fused_kernel<<<(NE + 255) / 256, 256>>>(edge_idx, edge_attr);

    const int aggr_blocks = (NN * 32 + 127) / 128;   // 12500: warp per node, 128-thr blocks

    const float* xin = x;
    for (int l = 0; l < 3; l++) {
        float* aggr = (l == 1) ? bufB : bufA;
        float* xout = (l == 0) ? bufA : ((l == 1) ? bufB : out);

        aggr_kernel<<<aggr_blocks, 128>>>(xin, We + l * ED * DD,
                                          be + l * DD, eps, l, aggr);
        mlp_kernel<<<148, 512, MLP_SMEM_BYTES>>>(
            aggr, W1 + l * DD * DD, b1 + l * DD,
            W2 + l * DD * DD, b2 + l * DD, xout);
        xin = xout;
    }
}

// round 13
// speedup vs baseline: 1.3853x; 1.0102x over previous
#include <cuda_runtime.h>
#include <math.h>

#define NN 50000
#define NE 800000
#define DD 128
#define ED 16
#define SCAN_NBLK ((NN + 1023) / 1024)   // 49

// Scratch (allocation-free rule: __device__ globals)
__device__ float g_bufA[NN * DD];
__device__ float g_bufB[NN * DD];
__device__ int   g_idx64;
__device__ int   g_cnt[NN];
__device__ int   g_rowptr[NN + 1];
__device__ int   g_cursor[NN];
__device__ int   g_blocksum[SCAN_NBLK];
__device__ int   g_blockoff[SCAN_NBLK];
__device__ int   g_src[NE];              // src node, dst-sorted
__device__ float g_eattr[NE * ED];       // edge_attr rows in dst-sorted order

// ---------------------------------------------------------------------------
// tf32 helpers
// ---------------------------------------------------------------------------
__device__ __forceinline__ void tf32split(float v, unsigned& hi, unsigned& lo) {
    asm("cvt.rna.tf32.f32 %0, %1;" : "=r"(hi) : "f"(v));
    float r = v - __uint_as_float(hi);
    asm("cvt.rna.tf32.f32 %0, %1;" : "=r"(lo) : "f"(r));
}

__device__ __forceinline__ void mma_tf32(float* d, const unsigned* a, const unsigned* b) {
    asm volatile(
        "mma.sync.aligned.m16n8k8.row.col.f32.tf32.tf32.f32 "
        "{%0,%1,%2,%3}, {%4,%5,%6,%7}, {%8,%9}, {%0,%1,%2,%3};"
        : "+f"(d[0]), "+f"(d[1]), "+f"(d[2]), "+f"(d[3])
        : "r"(a[0]), "r"(a[1]), "r"(a[2]), "r"(a[3]), "r"(b[0]), "r"(b[1]));
}

// ---------------------------------------------------------------------------
// Detect int64 vs int32 edge_idx (one warp, ballot)
// ---------------------------------------------------------------------------
__global__ void detect_idx_kernel(const long long* __restrict__ idx) {
    int lane = threadIdx.x;
    long long v = idx[lane];
    int bad = (v < 0 || v >= (long long)NN) ? 1 : 0;
    unsigned m = __ballot_sync(0xffffffffu, bad);
    if (lane == 0) g_idx64 = (m == 0u);
}

// ---------------------------------------------------------------------------
// CSR build
// ---------------------------------------------------------------------------
__global__ void zero_cnt_kernel() {
    int i = blockIdx.x * blockDim.x + threadIdx.x;
    if (i < NN) g_cnt[i] = 0;
}

__global__ void hist_kernel(const void* __restrict__ edge_idx) {
    int e = blockIdx.x * blockDim.x + threadIdx.x;
    if (e >= NE) return;
    int dst;
    if (g_idx64) dst = (int)((const long long*)edge_idx)[NE + e];
    else         dst = ((const int*)edge_idx)[NE + e];
    atomicAdd(&g_cnt[dst], 1);
}

__global__ void local_scan_kernel() {
    __shared__ int sdata[1024];
    int i = blockIdx.x * 1024 + threadIdx.x;
    int v = (i < NN) ? g_cnt[i] : 0;
    sdata[threadIdx.x] = v;
    __syncthreads();
    #pragma unroll
    for (int off = 1; off < 1024; off <<= 1) {
        int t = (threadIdx.x >= off) ? sdata[threadIdx.x - off] : 0;
        __syncthreads();
        sdata[threadIdx.x] += t;
        __syncthreads();
    }
    if (i < NN) g_rowptr[i] = sdata[threadIdx.x] - v;   // local exclusive
    if (threadIdx.x == 1023) g_blocksum[blockIdx.x] = sdata[1023];
}

__global__ void scan_sums_kernel() {
    __shared__ int sd[64];
    int t = threadIdx.x;
    int v = (t < SCAN_NBLK) ? g_blocksum[t] : 0;
    sd[t] = v;
    __syncthreads();
    #pragma unroll
    for (int off = 1; off < 64; off <<= 1) {
        int u = (t >= off) ? sd[t - off] : 0;
        __syncthreads();
        sd[t] += u;
        __syncthreads();
    }
    if (t < SCAN_NBLK) g_blockoff[t] = sd[t] - v;   // exclusive
}

__global__ void add_off_kernel() {
    int i = blockIdx.x * 1024 + threadIdx.x;
    if (i < NN) {
        int v = g_rowptr[i] + g_blockoff[blockIdx.x];
        g_rowptr[i] = v;
        g_cursor[i] = v;
    }
    if (i == 0) g_rowptr[NN] = NE;
}

// Fused scatter: place src AND the edge_attr row directly into dst-sorted order.
__global__ void scatter_fused_kernel(const void* __restrict__ edge_idx,
                                     const float* __restrict__ edge_attr) {
    int e = blockIdx.x * blockDim.x + threadIdx.x;
    if (e >= NE) return;
    int src, dst;
    if (g_idx64) {
        src = (int)((const long long*)edge_idx)[e];
        dst = (int)((const long long*)edge_idx)[NE + e];
    } else {
        src = ((const int*)edge_idx)[e];
        dst = ((const int*)edge_idx)[NE + e];
    }
    const float4* ea = (const float4*)(edge_attr + (size_t)e * ED);
    float4 a0 = ea[0], a1 = ea[1], a2 = ea[2], a3 = ea[3];
    int pos = atomicAdd(&g_cursor[dst], 1);
    g_src[pos] = src;
    float4* dstp = (float4*)(g_eattr + (size_t)pos * ED);
    dstp[0] = a0; dstp[1] = a1; dstp[2] = a2; dstp[3] = a3;
}

// ---------------------------------------------------------------------------
// Edge aggregation (CSR, no atomics): one warp per dst node (R9 body).
// 96-thread blocks, __launch_bounds__(96,5) -> 5 blocks/SM = 15 warps/SM
// (3.75 warps/SMSP), same per-warp work and traffic as R12.
// ---------------------------------------------------------------------------
#define MCHAIN(m, t0, t1, t2, t3)                                              \
    m.x += t0.x*w[0].x;  m.y += t0.x*w[0].y;  m.z += t0.x*w[0].z;  m.w += t0.x*w[0].w;  \
    m.x += t0.y*w[1].x;  m.y += t0.y*w[1].y;  m.z += t0.y*w[1].z;  m.w += t0.y*w[1].w;  \
    m.x += t0.z*w[2].x;  m.y += t0.z*w[2].y;  m.z += t0.z*w[2].z;  m.w += t0.z*w[2].w;  \
    m.x += t0.w*w[3].x;  m.y += t0.w*w[3].y;  m.z += t0.w*w[3].z;  m.w += t0.w*w[3].w;  \
    m.x += t1.x*w[4].x;  m.y += t1.x*w[4].y;  m.z += t1.x*w[4].z;  m.w += t1.x*w[4].w;  \
    m.x += t1.y*w[5].x;  m.y += t1.y*w[5].y;  m.z += t1.y*w[5].z;  m.w += t1.y*w[5].w;  \
    m.x += t1.z*w[6].x;  m.y += t1.z*w[6].y;  m.z += t1.z*w[6].z;  m.w += t1.z*w[6].w;  \
    m.x += t1.w*w[7].x;  m.y += t1.w*w[7].y;  m.z += t1.w*w[7].z;  m.w += t1.w*w[7].w;  \
    m.x += t2.x*w[8].x;  m.y += t2.x*w[8].y;  m.z += t2.x*w[8].z;  m.w += t2.x*w[8].w;  \
    m.x += t2.y*w[9].x;  m.y += t2.y*w[9].y;  m.z += t2.y*w[9].z;  m.w += t2.y*w[9].w;  \
    m.x += t2.z*w[10].x; m.y += t2.z*w[10].y; m.z += t2.z*w[10].z; m.w += t2.z*w[10].w; \
    m.x += t2.w*w[11].x; m.y += t2.w*w[11].y; m.z += t2.w*w[11].z; m.w += t2.w*w[11].w; \
    m.x += t3.x*w[12].x; m.y += t3.x*w[12].y; m.z += t3.x*w[12].z; m.w += t3.x*w[12].w; \
    m.x += t3.y*w[13].x; m.y += t3.y*w[13].y; m.z += t3.y*w[13].z; m.w += t3.y*w[13].w; \
    m.x += t3.z*w[14].x; m.y += t3.z*w[14].y; m.z += t3.z*w[14].z; m.w += t3.z*w[14].w; \
    m.x += t3.w*w[15].x; m.y += t3.w*w[15].y; m.z += t3.w*w[15].z; m.w += t3.w*w[15].w;

__global__ void __launch_bounds__(96, 5)
aggr_kernel(const float* __restrict__ xin,
            const float* __restrict__ We,
            const float* __restrict__ be,
            const float* __restrict__ eps, int l,
            float* __restrict__ aggr) {
    int lane = threadIdx.x & 31;
    int warp = (blockIdx.x * blockDim.x + threadIdx.x) >> 5;
    int nwarps = (gridDim.x * blockDim.x) >> 5;
    int c0 = lane * 4;

    float4 w[ED];
    #pragma unroll
    for (int k = 0; k < ED; k++)
        w[k] = *(const float4*)(We + k * DD + c0);
    float4 bias = *(const float4*)(be + c0);
    float s = 1.0f + eps[l];

    for (int d = warp; d < NN; d += nwarps) {
        float4 xv = *(const float4*)(xin + (size_t)d * DD + c0);
        float4 acc = make_float4(xv.x * s, xv.y * s, xv.z * s, xv.w * s);
        int beg = g_rowptr[d], end = g_rowptr[d + 1];

        int j = beg;
        for (; j + 1 < end; j += 2) {
            int s0 = g_src[j];
            int s1 = g_src[j + 1];
            const float4* p0 = (const float4*)(g_eattr + (size_t)j * ED);
            float4 a0 = p0[0], a1 = p0[1], a2 = p0[2], a3 = p0[3];
            float4 b0 = p0[4], b1 = p0[5], b2 = p0[6], b3 = p0[7];
            float4 xs0 = *(const float4*)(xin + (size_t)s0 * DD + c0);
            float4 xs1 = *(const float4*)(xin + (size_t)s1 * DD + c0);

            float4 m0 = bias;
            MCHAIN(m0, a0, a1, a2, a3)
            float4 m1 = bias;
            MCHAIN(m1, b0, b1, b2, b3)

            acc.x += fmaxf(m0.x + xs0.x, 0.0f) + fmaxf(m1.x + xs1.x, 0.0f);
            acc.y += fmaxf(m0.y + xs0.y, 0.0f) + fmaxf(m1.y + xs1.y, 0.0f);
            acc.z += fmaxf(m0.z + xs0.z, 0.0f) + fmaxf(m1.z + xs1.z, 0.0f);
            acc.w += fmaxf(m0.w + xs0.w, 0.0f) + fmaxf(m1.w + xs1.w, 0.0f);
        }
        if (j < end) {
            int s0 = g_src[j];
            const float4* p0 = (const float4*)(g_eattr + (size_t)j * ED);
            float4 a0 = p0[0], a1 = p0[1], a2 = p0[2], a3 = p0[3];
            float4 xs0 = *(const float4*)(xin + (size_t)s0 * DD + c0);
            float4 m0 = bias;
            MCHAIN(m0, a0, a1, a2, a3)
            acc.x += fmaxf(m0.x + xs0.x, 0.0f);
            acc.y += fmaxf(m0.y + xs0.y, 0.0f);
            acc.z += fmaxf(m0.z + xs0.z, 0.0f);
            acc.w += fmaxf(m0.w + xs0.w, 0.0f);
        }
        *(float4*)(aggr + (size_t)d * DD + c0) = acc;
    }
}

// ---------------------------------------------------------------------------
// Fused node MLP with tf32 tensor cores (3-way split) — unchanged from R12.
// Persistent, grid=148, 512 threads (16 warps, 4x4 warp grid).
// ---------------------------------------------------------------------------
#define PITCH 132
#define MLP_TILES ((NN + 127) / 128)     // 391
#define MLP_SMEM_FLOATS (3 * 128 * PITCH + 256)
#define MLP_SMEM_BYTES (MLP_SMEM_FLOATS * 4)

__global__ void __launch_bounds__(512)
mlp_kernel(const float* __restrict__ A,
           const float* __restrict__ W1g,
           const float* __restrict__ b1g,
           const float* __restrict__ W2g,
           const float* __restrict__ b2g,
           float* __restrict__ C) {
    extern __shared__ float sm[];
    float* sA   = sm;
    float* sW1T = sm + 128 * PITCH;
    float* sW2T = sW1T + 128 * PITCH;
    float* sb1  = sW2T + 128 * PITCH;
    float* sb2  = sb1 + 128;

    int tid = threadIdx.x;

    for (int i = tid; i < 128 * 128; i += 512) {
        int k = i >> 7, n = i & 127;
        sW1T[n * PITCH + k] = W1g[i];
        sW2T[n * PITCH + k] = W2g[i];
    }
    if (tid < 128) { sb1[tid] = b1g[tid]; sb2[tid] = b2g[tid]; }

    int lane = tid & 31, wid = tid >> 5;
    int g = lane >> 2, c = lane & 3;
    int wm = wid & 3, wn = wid >> 2;
    int mrow = wm * 32;
    int ncol = wn * 32;

    for (int tile = blockIdx.x; tile < MLP_TILES; tile += gridDim.x) {
        int row0 = tile * 128;

        __syncthreads();
        for (int i = tid; i < 128 * 32; i += 512) {
            int r = i >> 5, k4 = i & 31;
            int gr = row0 + r;
            float4 v = (gr < NN) ? ((const float4*)(A + (size_t)gr * DD))[k4]
                                 : make_float4(0.f, 0.f, 0.f, 0.f);
            *(float4*)(sA + r * PITCH + k4 * 4) = v;
        }
        __syncthreads();

        float acc[2][4][4];
        #pragma unroll
        for (int mt = 0; mt < 2; mt++)
            #pragma unroll
            for (int j = 0; j < 4; j++)
                #pragma unroll
                for (int q = 0; q < 4; q++) acc[mt][j][q] = 0.0f;

        #pragma unroll 1
        for (int s = 0; s < 16; s++) {
            int k0 = s * 8;
            unsigned bhi[4][2], blo[4][2];
            #pragma unroll
            for (int j = 0; j < 4; j++) {
                const float* bp = sW1T + (ncol + 8 * j + g) * PITCH + k0;
                tf32split(bp[c],     bhi[j][0], blo[j][0]);
                tf32split(bp[c + 4], bhi[j][1], blo[j][1]);
            }
            unsigned ahi[2][4], alo[2][4];
            #pragma unroll
            for (int mt = 0; mt < 2; mt++) {
                int r = mrow + mt * 16 + g;
                const float* a0p = sA + r * PITCH + k0;
                const float* a1p = sA + (r + 8) * PITCH + k0;
                tf32split(a0p[c],     ahi[mt][0], alo[mt][0]);
                tf32split(a1p[c],     ahi[mt][1], alo[mt][1]);
                tf32split(a0p[c + 4], ahi[mt][2], alo[mt][2]);
                tf32split(a1p[c + 4], ahi[mt][3], alo[mt][3]);
            }
            #pragma unroll
            for (int mt = 0; mt < 2; mt++)
                #pragma unroll
                for (int j = 0; j < 4; j++) mma_tf32(acc[mt][j], ahi[mt], bhi[j]);
            #pragma unroll
            for (int mt = 0; mt < 2; mt++)
                #pragma unroll
                for (int j = 0; j < 4; j++) mma_tf32(acc[mt][j], ahi[mt], blo[j]);
            #pragma unroll
            for (int mt = 0; mt < 2; mt++)
                #pragma unroll
                for (int j = 0; j < 4; j++) mma_tf32(acc[mt][j], alo[mt], bhi[j]);
        }
        __syncthreads();

        #pragma unroll
        for (int mt = 0; mt < 2; mt++) {
            int r = mrow + mt * 16 + g;
            #pragma unroll
            for (int j = 0; j < 4; j++) {
                int col = ncol + 8 * j + 2 * c;
                float h0 = acc[mt][j][0] + sb1[col];
                float h1 = acc[mt][j][1] + sb1[col + 1];
                float h2 = acc[mt][j][2] + sb1[col];
                float h3 = acc[mt][j][3] + sb1[col + 1];
                h0 = 0.5f * h0 * (1.0f + erff(h0 * 0.70710678118654752f));
                h1 = 0.5f * h1 * (1.0f + erff(h1 * 0.70710678118654752f));
                h2 = 0.5f * h2 * (1.0f + erff(h2 * 0.70710678118654752f));
                h3 = 0.5f * h3 * (1.0f + erff(h3 * 0.70710678118654752f));
                *(float2*)(sA + r * PITCH + col) = make_float2(h0, h1);
                *(float2*)(sA + (r + 8) * PITCH + col) = make_float2(h2, h3);
                acc[mt][j][0] = 0.0f; acc[mt][j][1] = 0.0f;
                acc[mt][j][2] = 0.0f; acc[mt][j][3] = 0.0f;
            }
        }
        __syncthreads();

        #pragma unroll 1
        for (int s = 0; s < 16; s++) {
            int k0 = s * 8;
            unsigned bhi[4][2], blo[4][2];
            #pragma unroll
            for (int j = 0; j < 4; j++) {
                const float* bp = sW2T + (ncol + 8 * j + g) * PITCH + k0;
                tf32split(bp[c],     bhi[j][0], blo[j][0]);
                tf32split(bp[c + 4], bhi[j][1], blo[j][1]);
            }
            unsigned ahi[2][4], alo[2][4];
            #pragma unroll
            for (int mt = 0; mt < 2; mt++) {
                int r = mrow + mt * 16 + g;
                const float* a0p = sA + r * PITCH + k0;
                const float* a1p = sA + (r + 8) * PITCH + k0;
                tf32split(a0p[c],     ahi[mt][0], alo[mt][0]);
                tf32split(a1p[c],     ahi[mt][1], alo[mt][1]);
                tf32split(a0p[c + 4], ahi[mt][2], alo[mt][2]);
                tf32split(a1p[c + 4], ahi[mt][3], alo[mt][3]);
            }
            #pragma unroll
            for (int mt = 0; mt < 2; mt++)
                #pragma unroll
                for (int j = 0; j < 4; j++) mma_tf32(acc[mt][j], ahi[mt], bhi[j]);
            #pragma unroll
            for (int mt = 0; mt < 2; mt++)
                #pragma unroll
                for (int j = 0; j < 4; j++) mma_tf32(acc[mt][j], ahi[mt], blo[j]);
            #pragma unroll
            for (int mt = 0; mt < 2; mt++)
                #pragma unroll
                for (int j = 0; j < 4; j++) mma_tf32(acc[mt][j], alo[mt], bhi[j]);
        }

        #pragma unroll
        for (int mt = 0; mt < 2; mt++) {
            int r = mrow + mt * 16 + g;
            int gr0 = row0 + r, gr1 = row0 + r + 8;
            #pragma unroll
            for (int j = 0; j < 4; j++) {
                int col = ncol + 8 * j + 2 * c;
                if (gr0 < NN)
                    *(float2*)(C + (size_t)gr0 * DD + col) =
                        make_float2(acc[mt][j][0] + sb2[col],
                                    acc[mt][j][1] + sb2[col + 1]);
                if (gr1 < NN)
                    *(float2*)(C + (size_t)gr1 * DD + col) =
                        make_float2(acc[mt][j][2] + sb2[col],
                                    acc[mt][j][3] + sb2[col + 1]);
            }
        }
    }
}

// ---------------------------------------------------------------------------
// Launch
// ---------------------------------------------------------------------------
extern "C" void kernel_launch(void* const* d_in, const int* in_sizes, int n_in,
                              void* d_out, int out_size) {
    const float* x         = (const float*)d_in[0];
    const float* edge_attr = (const float*)d_in[1];
    const float* W1        = (const float*)d_in[2];
    const float* b1        = (const float*)d_in[3];
    const float* W2        = (const float*)d_in[4];
    const float* b2        = (const float*)d_in[5];
    const float* We        = (const float*)d_in[6];
    const float* be        = (const float*)d_in[7];
    const float* eps       = (const float*)d_in[8];
    const void*  edge_idx  = d_in[9];
    float* out = (float*)d_out;

    float *bufA, *bufB;
    cudaGetSymbolAddress((void**)&bufA, g_bufA);
    cudaGetSymbolAddress((void**)&bufB, g_bufB);

    cudaFuncSetAttribute(mlp_kernel,
                         cudaFuncAttributeMaxDynamicSharedMemorySize,
                         MLP_SMEM_BYTES);

    // ---- CSR build + attr pre-sort (once per launch) ----
    detect_idx_kernel<<<1, 32>>>((const long long*)edge_idx);
    zero_cnt_kernel<<<(NN + 255) / 256, 256>>>();
    hist_kernel<<<(NE + 255) / 256, 256>>>(edge_idx);
    local_scan_kernel<<<SCAN_NBLK, 1024>>>();
    scan_sums_kernel<<<1, 64>>>();
    add_off_kernel<<<SCAN_NBLK, 1024>>>();
    scatter_fused_kernel<<<(NE + 255) / 256, 256>>>(edge_idx, edge_attr);

    const int aggr_blocks = (NN * 32 + 95) / 96;   // warp per node, 96-thr blocks

    const float* xin = x;
    for (int l = 0; l < 3; l++) {
        float* aggr = (l == 1) ? bufB : bufA;
        float* xout = (l == 0) ? bufA : ((l == 1) ? bufB : out);

        aggr_kernel<<<aggr_blocks, 96>>>(xin, We + l * ED * DD,
                                         be + l * DD, eps, l, aggr);
        mlp_kernel<<<148, 512, MLP_SMEM_BYTES>>>(
            aggr, W1 + l * DD * DD, b1 + l * DD,
            W2 + l * DD * DD, b2 + l * DD, xout);
        xin = xout;
    }
}

// round 14
// speedup vs baseline: 1.5718x; 1.1346x over previous
#include <cuda_runtime.h>
#include <cuda_bf16.h>
#include <math.h>

#define NN 50000
#define NE 800000
#define DD 128
#define ED 16
#define SCAN_NBLK ((NN + 1023) / 1024)   // 49

// Scratch (allocation-free rule: __device__ globals)
__device__ float g_bufA[NN * DD];
__device__ float g_bufB[NN * DD];
__device__ int   g_idx64;
__device__ int   g_cnt[NN];
__device__ int   g_rowptr[NN + 1];
__device__ int   g_cursor[NN];
__device__ int   g_blocksum[SCAN_NBLK];
__device__ int   g_blockoff[SCAN_NBLK];
__device__ int   g_src[NE];              // src node, dst-sorted
__device__ float g_eattr[NE * ED];       // edge_attr rows in dst-sorted order

// ---------------------------------------------------------------------------
// bf16 split helpers (Ootomo 2-term split; 3-product MMA ~ fp32 accuracy)
// ---------------------------------------------------------------------------
__device__ __forceinline__ unsigned pack_bf16x2(float lo, float hi) {
    unsigned r;
    asm("cvt.rn.bf16x2.f32 %0, %1, %2;" : "=r"(r) : "f"(hi), "f"(lo));
    return r;   // low 16 bits = bf16(lo), high 16 = bf16(hi)
}
__device__ __forceinline__ void bf16split2(float v0, float v1,
                                           unsigned& hi, unsigned& mid) {
    hi = pack_bf16x2(v0, v1);
    float r0 = v0 - __uint_as_float(hi << 16);
    float r1 = v1 - __uint_as_float(hi & 0xffff0000u);
    mid = pack_bf16x2(r0, r1);
}

__device__ __forceinline__ void mma_bf16(float* d, const unsigned* a, const unsigned* b) {
    asm volatile(
        "mma.sync.aligned.m16n8k16.row.col.f32.bf16.bf16.f32 "
        "{%0,%1,%2,%3}, {%4,%5,%6,%7}, {%8,%9}, {%0,%1,%2,%3};"
        : "+f"(d[0]), "+f"(d[1]), "+f"(d[2]), "+f"(d[3])
        : "r"(a[0]), "r"(a[1]), "r"(a[2]), "r"(a[3]), "r"(b[0]), "r"(b[1]));
}

// ---------------------------------------------------------------------------
// Detect int64 vs int32 edge_idx (one warp, ballot)
// ---------------------------------------------------------------------------
__global__ void detect_idx_kernel(const long long* __restrict__ idx) {
    int lane = threadIdx.x;
    long long v = idx[lane];
    int bad = (v < 0 || v >= (long long)NN) ? 1 : 0;
    unsigned m = __ballot_sync(0xffffffffu, bad);
    if (lane == 0) g_idx64 = (m == 0u);
}

// ---------------------------------------------------------------------------
// CSR build
// ---------------------------------------------------------------------------
__global__ void zero_cnt_kernel() {
    int i = blockIdx.x * blockDim.x + threadIdx.x;
    if (i < NN) g_cnt[i] = 0;
}

__global__ void hist_kernel(const void* __restrict__ edge_idx) {
    int e = blockIdx.x * blockDim.x + threadIdx.x;
    if (e >= NE) return;
    int dst;
    if (g_idx64) dst = (int)((const long long*)edge_idx)[NE + e];
    else         dst = ((const int*)edge_idx)[NE + e];
    atomicAdd(&g_cnt[dst], 1);
}

__global__ void local_scan_kernel() {
    __shared__ int sdata[1024];
    int i = blockIdx.x * 1024 + threadIdx.x;
    int v = (i < NN) ? g_cnt[i] : 0;
    sdata[threadIdx.x] = v;
    __syncthreads();
    #pragma unroll
    for (int off = 1; off < 1024; off <<= 1) {
        int t = (threadIdx.x >= off) ? sdata[threadIdx.x - off] : 0;
        __syncthreads();
        sdata[threadIdx.x] += t;
        __syncthreads();
    }
    if (i < NN) g_rowptr[i] = sdata[threadIdx.x] - v;   // local exclusive
    if (threadIdx.x == 1023) g_blocksum[blockIdx.x] = sdata[1023];
}

__global__ void scan_sums_kernel() {
    __shared__ int sd[64];
    int t = threadIdx.x;
    int v = (t < SCAN_NBLK) ? g_blocksum[t] : 0;
    sd[t] = v;
    __syncthreads();
    #pragma unroll
    for (int off = 1; off < 64; off <<= 1) {
        int u = (t >= off) ? sd[t - off] : 0;
        __syncthreads();
        sd[t] += u;
        __syncthreads();
    }
    if (t < SCAN_NBLK) g_blockoff[t] = sd[t] - v;   // exclusive
}

__global__ void add_off_kernel() {
    int i = blockIdx.x * 1024 + threadIdx.x;
    if (i < NN) {
        int v = g_rowptr[i] + g_blockoff[blockIdx.x];
        g_rowptr[i] = v;
        g_cursor[i] = v;
    }
    if (i == 0) g_rowptr[NN] = NE;
}

// Fused scatter: place src AND the edge_attr row directly into dst-sorted order.
__global__ void scatter_fused_kernel(const void* __restrict__ edge_idx,
                                     const float* __restrict__ edge_attr) {
    int e = blockIdx.x * blockDim.x + threadIdx.x;
    if (e >= NE) return;
    int src, dst;
    if (g_idx64) {
        src = (int)((const long long*)edge_idx)[e];
        dst = (int)((const long long*)edge_idx)[NE + e];
    } else {
        src = ((const int*)edge_idx)[e];
        dst = ((const int*)edge_idx)[NE + e];
    }
    const float4* ea = (const float4*)(edge_attr + (size_t)e * ED);
    float4 a0 = ea[0], a1 = ea[1], a2 = ea[2], a3 = ea[3];
    int pos = atomicAdd(&g_cursor[dst], 1);
    g_src[pos] = src;
    float4* dstp = (float4*)(g_eattr + (size_t)pos * ED);
    dstp[0] = a0; dstp[1] = a1; dstp[2] = a2; dstp[3] = a3;
}

// ---------------------------------------------------------------------------
// Edge aggregation (CSR, no atomics): one warp per dst node (R13 known-good).
// 96-thread blocks, 5 blocks/SM.
// ---------------------------------------------------------------------------
#define MCHAIN(m, t0, t1, t2, t3)                                              \
    m.x += t0.x*w[0].x;  m.y += t0.x*w[0].y;  m.z += t0.x*w[0].z;  m.w += t0.x*w[0].w;  \
    m.x += t0.y*w[1].x;  m.y += t0.y*w[1].y;  m.z += t0.y*w[1].z;  m.w += t0.y*w[1].w;  \
    m.x += t0.z*w[2].x;  m.y += t0.z*w[2].y;  m.z += t0.z*w[2].z;  m.w += t0.z*w[2].w;  \
    m.x += t0.w*w[3].x;  m.y += t0.w*w[3].y;  m.z += t0.w*w[3].z;  m.w += t0.w*w[3].w;  \
    m.x += t1.x*w[4].x;  m.y += t1.x*w[4].y;  m.z += t1.x*w[4].z;  m.w += t1.x*w[4].w;  \
    m.x += t1.y*w[5].x;  m.y += t1.y*w[5].y;  m.z += t1.y*w[5].z;  m.w += t1.y*w[5].w;  \
    m.x += t1.z*w[6].x;  m.y += t1.z*w[6].y;  m.z += t1.z*w[6].z;  m.w += t1.z*w[6].w;  \
    m.x += t1.w*w[7].x;  m.y += t1.w*w[7].y;  m.z += t1.w*w[7].z;  m.w += t1.w*w[7].w;  \
    m.x += t2.x*w[8].x;  m.y += t2.x*w[8].y;  m.z += t2.x*w[8].z;  m.w += t2.x*w[8].w;  \
    m.x += t2.y*w[9].x;  m.y += t2.y*w[9].y;  m.z += t2.y*w[9].z;  m.w += t2.y*w[9].w;  \
    m.x += t2.z*w[10].x; m.y += t2.z*w[10].y; m.z += t2.z*w[10].z; m.w += t2.z*w[10].w; \
    m.x += t2.w*w[11].x; m.y += t2.w*w[11].y; m.z += t2.w*w[11].z; m.w += t2.w*w[11].w; \
    m.x += t3.x*w[12].x; m.y += t3.x*w[12].y; m.z += t3.x*w[12].z; m.w += t3.x*w[12].w; \
    m.x += t3.y*w[13].x; m.y += t3.y*w[13].y; m.z += t3.y*w[13].z; m.w += t3.y*w[13].w; \
    m.x += t3.z*w[14].x; m.y += t3.z*w[14].y; m.z += t3.z*w[14].z; m.w += t3.z*w[14].w; \
    m.x += t3.w*w[15].x; m.y += t3.w*w[15].y; m.z += t3.w*w[15].z; m.w += t3.w*w[15].w;

__global__ void __launch_bounds__(96, 5)
aggr_kernel(const float* __restrict__ xin,
            const float* __restrict__ We,
            const float* __restrict__ be,
            const float* __restrict__ eps, int l,
            float* __restrict__ aggr) {
    int lane = threadIdx.x & 31;
    int warp = (blockIdx.x * blockDim.x + threadIdx.x) >> 5;
    int nwarps = (gridDim.x * blockDim.x) >> 5;
    int c0 = lane * 4;

    float4 w[ED];
    #pragma unroll
    for (int k = 0; k < ED; k++)
        w[k] = *(const float4*)(We + k * DD + c0);
    float4 bias = *(const float4*)(be + c0);
    float s = 1.0f + eps[l];

    for (int d = warp; d < NN; d += nwarps) {
        float4 xv = *(const float4*)(xin + (size_t)d * DD + c0);
        float4 acc = make_float4(xv.x * s, xv.y * s, xv.z * s, xv.w * s);
        int beg = g_rowptr[d], end = g_rowptr[d + 1];

        int j = beg;
        for (; j + 1 < end; j += 2) {
            int s0 = g_src[j];
            int s1 = g_src[j + 1];
            const float4* p0 = (const float4*)(g_eattr + (size_t)j * ED);
            float4 a0 = p0[0], a1 = p0[1], a2 = p0[2], a3 = p0[3];
            float4 b0 = p0[4], b1 = p0[5], b2 = p0[6], b3 = p0[7];
            float4 xs0 = *(const float4*)(xin + (size_t)s0 * DD + c0);
            float4 xs1 = *(const float4*)(xin + (size_t)s1 * DD + c0);

            float4 m0 = bias;
            MCHAIN(m0, a0, a1, a2, a3)
            float4 m1 = bias;
            MCHAIN(m1, b0, b1, b2, b3)

            acc.x += fmaxf(m0.x + xs0.x, 0.0f) + fmaxf(m1.x + xs1.x, 0.0f);
            acc.y += fmaxf(m0.y + xs0.y, 0.0f) + fmaxf(m1.y + xs1.y, 0.0f);
            acc.z += fmaxf(m0.z + xs0.z, 0.0f) + fmaxf(m1.z + xs1.z, 0.0f);
            acc.w += fmaxf(m0.w + xs0.w, 0.0f) + fmaxf(m1.w + xs1.w, 0.0f);
        }
        if (j < end) {
            int s0 = g_src[j];
            const float4* p0 = (const float4*)(g_eattr + (size_t)j * ED);
            float4 a0 = p0[0], a1 = p0[1], a2 = p0[2], a3 = p0[3];
            float4 xs0 = *(const float4*)(xin + (size_t)s0 * DD + c0);
            float4 m0 = bias;
            MCHAIN(m0, a0, a1, a2, a3)
            acc.x += fmaxf(m0.x + xs0.x, 0.0f);
            acc.y += fmaxf(m0.y + xs0.y, 0.0f);
            acc.z += fmaxf(m0.z + xs0.z, 0.0f);
            acc.w += fmaxf(m0.w + xs0.w, 0.0f);
        }
        *(float4*)(aggr + (size_t)d * DD + c0) = acc;
    }
}

// ---------------------------------------------------------------------------
// Fused node MLP — bf16 3-product (hi*hi + hi*mid + mid*hi), m16n8k16.
// Persistent, grid=148, 512 threads (16 warps, 4x4 warp grid).
// All operands pre-split into packed bf16x2 smem arrays (weights once per
// block; A once per tile; H split inside epilogue 1). Inner loop = LDS + MMA.
// Fragment layout (m16n8k16, g=lane>>2, c=lane&3, k2 = k/2 packed pairs):
//   A: a0=[r][k2=c] a1=[r+8][c] a2=[r][c+4] a3=[r+8][c+4]
//   B: b0=[n][k2=c] b1=[n][c+4]
//   C: c0=(g,2c) c1=(g,2c+1) c2=(g+8,2c) c3=(g+8,2c+1)
// P2=68 -> bank = (4g + c) mod 32: conflict-free.
// ---------------------------------------------------------------------------
#define P2 68
#define MLP_TILES ((NN + 127) / 128)     // 391
#define MLP_SMEM_WORDS (6 * 128 * P2 + 256)
#define MLP_SMEM_BYTES (MLP_SMEM_WORDS * 4)

__global__ void __launch_bounds__(512)
mlp_kernel(const float* __restrict__ A,
           const float* __restrict__ W1g,
           const float* __restrict__ b1g,
           const float* __restrict__ W2g,
           const float* __restrict__ b2g,
           float* __restrict__ C) {
    extern __shared__ unsigned um[];
    unsigned* uAhi  = um;
    unsigned* uAmid = um + 128 * P2;
    unsigned* uW1hi = um + 2 * 128 * P2;
    unsigned* uW1mid= um + 3 * 128 * P2;
    unsigned* uW2hi = um + 4 * 128 * P2;
    unsigned* uW2mid= um + 5 * 128 * P2;
    float* sb1 = (float*)(um + 6 * 128 * P2);
    float* sb2 = sb1 + 128;

    int tid = threadIdx.x;

    // One-time: split weights into packed bf16x2 (transposed: [n][k2])
    for (int i = tid; i < 64 * 128; i += 512) {
        int k2 = i >> 7, n = i & 127;     // coalesced over n
        float w0 = W1g[(2 * k2) * 128 + n];
        float w1 = W1g[(2 * k2 + 1) * 128 + n];
        unsigned h, m;
        bf16split2(w0, w1, h, m);
        uW1hi[n * P2 + k2] = h; uW1mid[n * P2 + k2] = m;
        w0 = W2g[(2 * k2) * 128 + n];
        w1 = W2g[(2 * k2 + 1) * 128 + n];
        bf16split2(w0, w1, h, m);
        uW2hi[n * P2 + k2] = h; uW2mid[n * P2 + k2] = m;
    }
    if (tid < 128) { sb1[tid] = b1g[tid]; sb2[tid] = b2g[tid]; }

    int lane = tid & 31, wid = tid >> 5;
    int g = lane >> 2, c = lane & 3;
    int wm = wid & 3, wn = wid >> 2;      // warp grid 4 x 4
    int mrow = wm * 32;
    int ncol = wn * 32;

    for (int tile = blockIdx.x; tile < MLP_TILES; tile += gridDim.x) {
        int row0 = tile * 128;

        __syncthreads();   // previous iteration done reading uA*
        for (int i = tid; i < 128 * 32; i += 512) {
            int r = i >> 5, q = i & 31;   // q-th float4: k = 4q..4q+3
            int gr = row0 + r;
            float4 v = (gr < NN) ? ((const float4*)(A + (size_t)gr * DD))[q]
                                 : make_float4(0.f, 0.f, 0.f, 0.f);
            unsigned h0, m0, h1, m1;
            bf16split2(v.x, v.y, h0, m0);
            bf16split2(v.z, v.w, h1, m1);
            uAhi [r * P2 + 2 * q]     = h0;
            uAhi [r * P2 + 2 * q + 1] = h1;
            uAmid[r * P2 + 2 * q]     = m0;
            uAmid[r * P2 + 2 * q + 1] = m1;
        }
        __syncthreads();

        float acc[2][4][4];
        #pragma unroll
        for (int mt = 0; mt < 2; mt++)
            #pragma unroll
            for (int j = 0; j < 4; j++)
                #pragma unroll
                for (int q = 0; q < 4; q++) acc[mt][j][q] = 0.0f;

        // ---- GEMM1: A @ W1 (8 k-steps of 16) ----
        #pragma unroll 1
        for (int s = 0; s < 8; s++) {
            int k0 = s * 8;
            unsigned bh[4][2], bm[4][2];
            #pragma unroll
            for (int j = 0; j < 4; j++) {
                const unsigned* ph = uW1hi  + (ncol + 8 * j + g) * P2 + k0;
                const unsigned* pm = uW1mid + (ncol + 8 * j + g) * P2 + k0;
                bh[j][0] = ph[c]; bh[j][1] = ph[c + 4];
                bm[j][0] = pm[c]; bm[j][1] = pm[c + 4];
            }
            unsigned ah[2][4], am[2][4];
            #pragma unroll
            for (int mt = 0; mt < 2; mt++) {
                int r = mrow + mt * 16 + g;
                const unsigned* p0 = uAhi  + r * P2 + k0;
                const unsigned* p1 = uAhi  + (r + 8) * P2 + k0;
                const unsigned* q0 = uAmid + r * P2 + k0;
                const unsigned* q1 = uAmid + (r + 8) * P2 + k0;
                ah[mt][0] = p0[c]; ah[mt][1] = p1[c];
                ah[mt][2] = p0[c + 4]; ah[mt][3] = p1[c + 4];
                am[mt][0] = q0[c]; am[mt][1] = q1[c];
                am[mt][2] = q0[c + 4]; am[mt][3] = q1[c + 4];
            }
            #pragma unroll
            for (int mt = 0; mt < 2; mt++)
                #pragma unroll
                for (int j = 0; j < 4; j++) mma_bf16(acc[mt][j], ah[mt], bh[j]);
            #pragma unroll
            for (int mt = 0; mt < 2; mt++)
                #pragma unroll
                for (int j = 0; j < 4; j++) mma_bf16(acc[mt][j], ah[mt], bm[j]);
            #pragma unroll
            for (int mt = 0; mt < 2; mt++)
                #pragma unroll
                for (int j = 0; j < 4; j++) mma_bf16(acc[mt][j], am[mt], bh[j]);
        }
        __syncthreads();   // all warps done reading uA*

        // ---- epilogue 1: H = gelu_exact(D1 + b1) -> split into uAhi/uAmid --
        #pragma unroll
        for (int mt = 0; mt < 2; mt++) {
            int r = mrow + mt * 16 + g;
            #pragma unroll
            for (int j = 0; j < 4; j++) {
                int col = ncol + 8 * j + 2 * c;
                int k2 = (ncol >> 1) + 4 * j + c;
                float h0 = acc[mt][j][0] + sb1[col];
                float h1 = acc[mt][j][1] + sb1[col + 1];
                float h2 = acc[mt][j][2] + sb1[col];
                float h3 = acc[mt][j][3] + sb1[col + 1];
                h0 = 0.5f * h0 * (1.0f + erff(h0 * 0.70710678118654752f));
                h1 = 0.5f * h1 * (1.0f + erff(h1 * 0.70710678118654752f));
                h2 = 0.5f * h2 * (1.0f + erff(h2 * 0.70710678118654752f));
                h3 = 0.5f * h3 * (1.0f + erff(h3 * 0.70710678118654752f));
                unsigned hh, mm;
                bf16split2(h0, h1, hh, mm);
                uAhi[r * P2 + k2] = hh; uAmid[r * P2 + k2] = mm;
                bf16split2(h2, h3, hh, mm);
                uAhi[(r + 8) * P2 + k2] = hh; uAmid[(r + 8) * P2 + k2] = mm;
                acc[mt][j][0] = 0.0f; acc[mt][j][1] = 0.0f;
                acc[mt][j][2] = 0.0f; acc[mt][j][3] = 0.0f;
            }
        }
        __syncthreads();

        // ---- GEMM2: H @ W2 ----
        #pragma unroll 1
        for (int s = 0; s < 8; s++) {
            int k0 = s * 8;
            unsigned bh[4][2], bm[4][2];
            #pragma unroll
            for (int j = 0; j < 4; j++) {
                const unsigned* ph = uW2hi  + (ncol + 8 * j + g) * P2 + k0;
                const unsigned* pm = uW2mid + (ncol + 8 * j + g) * P2 + k0;
                bh[j][0] = ph[c]; bh[j][1] = ph[c + 4];
                bm[j][0] = pm[c]; bm[j][1] = pm[c + 4];
            }
            unsigned ah[2][4], am[2][4];
            #pragma unroll
            for (int mt = 0; mt < 2; mt++) {
                int r = mrow + mt * 16 + g;
                const unsigned* p0 = uAhi  + r * P2 + k0;
                const unsigned* p1 = uAhi  + (r + 8) * P2 + k0;
                const unsigned* q0 = uAmid + r * P2 + k0;
                const unsigned* q1 = uAmid + (r + 8) * P2 + k0;
                ah[mt][0] = p0[c]; ah[mt][1] = p1[c];
                ah[mt][2] = p0[c + 4]; ah[mt][3] = p1[c + 4];
                am[mt][0] = q0[c]; am[mt][1] = q1[c];
                am[mt][2] = q0[c + 4]; am[mt][3] = q1[c + 4];
            }
            #pragma unroll
            for (int mt = 0; mt < 2; mt++)
                #pragma unroll
                for (int j = 0; j < 4; j++) mma_bf16(acc[mt][j], ah[mt], bh[j]);
            #pragma unroll
            for (int mt = 0; mt < 2; mt++)
                #pragma unroll
                for (int j = 0; j < 4; j++) mma_bf16(acc[mt][j], ah[mt], bm[j]);
            #pragma unroll
            for (int mt = 0; mt < 2; mt++)
                #pragma unroll
                for (int j = 0; j < 4; j++) mma_bf16(acc[mt][j], am[mt], bh[j]);
        }

        // ---- epilogue 2: C = D2 + b2 ----
        #pragma unroll
        for (int mt = 0; mt < 2; mt++) {
            int r = mrow + mt * 16 + g;
            int gr0 = row0 + r, gr1 = row0 + r + 8;
            #pragma unroll
            for (int j = 0; j < 4; j++) {
                int col = ncol + 8 * j + 2 * c;
                if (gr0 < NN)
                    *(float2*)(C + (size_t)gr0 * DD + col) =
                        make_float2(acc[mt][j][0] + sb2[col],
                                    acc[mt][j][1] + sb2[col + 1]);
                if (gr1 < NN)
                    *(float2*)(C + (size_t)gr1 * DD + col) =
                        make_float2(acc[mt][j][2] + sb2[col],
                                    acc[mt][j][3] + sb2[col + 1]);
            }
        }
    }
}

// ---------------------------------------------------------------------------
// Launch
// ---------------------------------------------------------------------------
extern "C" void kernel_launch(void* const* d_in, const int* in_sizes, int n_in,
                              void* d_out, int out_size) {
    const float* x         = (const float*)d_in[0];
    const float* edge_attr = (const float*)d_in[1];
    const float* W1        = (const float*)d_in[2];
    const float* b1        = (const float*)d_in[3];
    const float* W2        = (const float*)d_in[4];
    const float* b2        = (const float*)d_in[5];
    const float* We        = (const float*)d_in[6];
    const float* be        = (const float*)d_in[7];
    const float* eps       = (const float*)d_in[8];
    const void*  edge_idx  = d_in[9];
    float* out = (float*)d_out;

    float *bufA, *bufB;
    cudaGetSymbolAddress((void**)&bufA, g_bufA);
    cudaGetSymbolAddress((void**)&bufB, g_bufB);

    cudaFuncSetAttribute(mlp_kernel,
                         cudaFuncAttributeMaxDynamicSharedMemorySize,
                         MLP_SMEM_BYTES);

    // ---- CSR build + attr pre-sort (once per launch) ----
    detect_idx_kernel<<<1, 32>>>((const long long*)edge_idx);
    zero_cnt_kernel<<<(NN + 255) / 256, 256>>>();
    hist_kernel<<<(NE + 255) / 256, 256>>>(edge_idx);
    local_scan_kernel<<<SCAN_NBLK, 1024>>>();
    scan_sums_kernel<<<1, 64>>>();
    add_off_kernel<<<SCAN_NBLK, 1024>>>();
    scatter_fused_kernel<<<(NE + 255) / 256, 256>>>(edge_idx, edge_attr);

    const int aggr_blocks = (NN * 32 + 95) / 96;   // warp per node, 96-thr blocks

    const float* xin = x;
    for (int l = 0; l < 3; l++) {
        float* aggr = (l == 1) ? bufB : bufA;
        float* xout = (l == 0) ? bufA : ((l == 1) ? bufB : out);

        aggr_kernel<<<aggr_blocks, 96>>>(xin, We + l * ED * DD,
                                         be + l * DD, eps, l, aggr);
        mlp_kernel<<<148, 512, MLP_SMEM_BYTES>>>(
            aggr, W1 + l * DD * DD, b1 + l * DD,
            W2 + l * DD * DD, b2 + l * DD, xout);
        xin = xout;
    }
}

// round 15
// speedup vs baseline: 1.5838x; 1.0076x over previous
#include <cuda_runtime.h>
#include <cuda_bf16.h>
#include <math.h>

#define NN 50000
#define NE 800000
#define DD 128
#define ED 16
#define SCAN_NBLK ((NN + 1023) / 1024)   // 49

// Scratch (allocation-free rule: __device__ globals)
__device__ float g_bufA[NN * DD];
__device__ float g_bufB[NN * DD];
__device__ int   g_idx64;
__device__ int   g_cnt[NN];
__device__ int   g_rowptr[NN + 1];
__device__ int   g_cursor[NN];
__device__ int   g_blocksum[SCAN_NBLK];
__device__ int   g_blockoff[SCAN_NBLK];
__device__ int   g_src[NE];              // src node, dst-sorted
__device__ float g_eattr[NE * ED];       // edge_attr rows in dst-sorted order

// ---------------------------------------------------------------------------
// bf16 split helpers (Ootomo 2-term split; 3-product MMA ~ fp32 accuracy)
// ---------------------------------------------------------------------------
__device__ __forceinline__ unsigned pack_bf16x2(float lo, float hi) {
    unsigned r;
    asm("cvt.rn.bf16x2.f32 %0, %1, %2;" : "=r"(r) : "f"(hi), "f"(lo));
    return r;   // low 16 bits = bf16(lo), high 16 = bf16(hi)
}
__device__ __forceinline__ void bf16split2(float v0, float v1,
                                           unsigned& hi, unsigned& mid) {
    hi = pack_bf16x2(v0, v1);
    float r0 = v0 - __uint_as_float(hi << 16);
    float r1 = v1 - __uint_as_float(hi & 0xffff0000u);
    mid = pack_bf16x2(r0, r1);
}

__device__ __forceinline__ void mma_bf16(float* d, const unsigned* a, const unsigned* b) {
    asm volatile(
        "mma.sync.aligned.m16n8k16.row.col.f32.bf16.bf16.f32 "
        "{%0,%1,%2,%3}, {%4,%5,%6,%7}, {%8,%9}, {%0,%1,%2,%3};"
        : "+f"(d[0]), "+f"(d[1]), "+f"(d[2]), "+f"(d[3])
        : "r"(a[0]), "r"(a[1]), "r"(a[2]), "r"(a[3]), "r"(b[0]), "r"(b[1]));
}

// ---------------------------------------------------------------------------
// Detect int64 vs int32 edge_idx (one warp, ballot)
// ---------------------------------------------------------------------------
__global__ void detect_idx_kernel(const long long* __restrict__ idx) {
    int lane = threadIdx.x;
    long long v = idx[lane];
    int bad = (v < 0 || v >= (long long)NN) ? 1 : 0;
    unsigned m = __ballot_sync(0xffffffffu, bad);
    if (lane == 0) g_idx64 = (m == 0u);
}

// ---------------------------------------------------------------------------
// CSR build
// ---------------------------------------------------------------------------
__global__ void zero_cnt_kernel() {
    int i = blockIdx.x * blockDim.x + threadIdx.x;
    if (i < NN) g_cnt[i] = 0;
}

__global__ void hist_kernel(const void* __restrict__ edge_idx) {
    int e = blockIdx.x * blockDim.x + threadIdx.x;
    if (e >= NE) return;
    int dst;
    if (g_idx64) dst = (int)((const long long*)edge_idx)[NE + e];
    else         dst = ((const int*)edge_idx)[NE + e];
    atomicAdd(&g_cnt[dst], 1);
}

__global__ void local_scan_kernel() {
    __shared__ int sdata[1024];
    int i = blockIdx.x * 1024 + threadIdx.x;
    int v = (i < NN) ? g_cnt[i] : 0;
    sdata[threadIdx.x] = v;
    __syncthreads();
    #pragma unroll
    for (int off = 1; off < 1024; off <<= 1) {
        int t = (threadIdx.x >= off) ? sdata[threadIdx.x - off] : 0;
        __syncthreads();
        sdata[threadIdx.x] += t;
        __syncthreads();
    }
    if (i < NN) g_rowptr[i] = sdata[threadIdx.x] - v;   // local exclusive
    if (threadIdx.x == 1023) g_blocksum[blockIdx.x] = sdata[1023];
}

__global__ void scan_sums_kernel() {
    __shared__ int sd[64];
    int t = threadIdx.x;
    int v = (t < SCAN_NBLK) ? g_blocksum[t] : 0;
    sd[t] = v;
    __syncthreads();
    #pragma unroll
    for (int off = 1; off < 64; off <<= 1) {
        int u = (t >= off) ? sd[t - off] : 0;
        __syncthreads();
        sd[t] += u;
        __syncthreads();
    }
    if (t < SCAN_NBLK) g_blockoff[t] = sd[t] - v;   // exclusive
}

__global__ void add_off_kernel() {
    int i = blockIdx.x * 1024 + threadIdx.x;
    if (i < NN) {
        int v = g_rowptr[i] + g_blockoff[blockIdx.x];
        g_rowptr[i] = v;
        g_cursor[i] = v;
    }
    if (i == 0) g_rowptr[NN] = NE;
}

// Fused scatter: place src AND the edge_attr row directly into dst-sorted order.
__global__ void scatter_fused_kernel(const void* __restrict__ edge_idx,
                                     const float* __restrict__ edge_attr) {
    int e = blockIdx.x * blockDim.x + threadIdx.x;
    if (e >= NE) return;
    int src, dst;
    if (g_idx64) {
        src = (int)((const long long*)edge_idx)[e];
        dst = (int)((const long long*)edge_idx)[NE + e];
    } else {
        src = ((const int*)edge_idx)[e];
        dst = ((const int*)edge_idx)[NE + e];
    }
    const float4* ea = (const float4*)(edge_attr + (size_t)e * ED);
    float4 a0 = ea[0], a1 = ea[1], a2 = ea[2], a3 = ea[3];
    int pos = atomicAdd(&g_cursor[dst], 1);
    g_src[pos] = src;
    float4* dstp = (float4*)(g_eattr + (size_t)pos * ED);
    dstp[0] = a0; dstp[1] = a1; dstp[2] = a2; dstp[3] = a3;
}

// ---------------------------------------------------------------------------
// Edge aggregation (CSR, no atomics): one warp per dst node, 96-thr blocks,
// 5 blocks/SM. NEW: next-iteration src indices prefetched before the FMA
// chain so the idx->gather dependency overlaps compute.
// ---------------------------------------------------------------------------
#define MCHAIN(m, t0, t1, t2, t3)                                              \
    m.x += t0.x*w[0].x;  m.y += t0.x*w[0].y;  m.z += t0.x*w[0].z;  m.w += t0.x*w[0].w;  \
    m.x += t0.y*w[1].x;  m.y += t0.y*w[1].y;  m.z += t0.y*w[1].z;  m.w += t0.y*w[1].w;  \
    m.x += t0.z*w[2].x;  m.y += t0.z*w[2].y;  m.z += t0.z*w[2].z;  m.w += t0.z*w[2].w;  \
    m.x += t0.w*w[3].x;  m.y += t0.w*w[3].y;  m.z += t0.w*w[3].z;  m.w += t0.w*w[3].w;  \
    m.x += t1.x*w[4].x;  m.y += t1.x*w[4].y;  m.z += t1.x*w[4].z;  m.w += t1.x*w[4].w;  \
    m.x += t1.y*w[5].x;  m.y += t1.y*w[5].y;  m.z += t1.y*w[5].z;  m.w += t1.y*w[5].w;  \
    m.x += t1.z*w[6].x;  m.y += t1.z*w[6].y;  m.z += t1.z*w[6].z;  m.w += t1.z*w[6].w;  \
    m.x += t1.w*w[7].x;  m.y += t1.w*w[7].y;  m.z += t1.w*w[7].z;  m.w += t1.w*w[7].w;  \
    m.x += t2.x*w[8].x;  m.y += t2.x*w[8].y;  m.z += t2.x*w[8].z;  m.w += t2.x*w[8].w;  \
    m.x += t2.y*w[9].x;  m.y += t2.y*w[9].y;  m.z += t2.y*w[9].z;  m.w += t2.y*w[9].w;  \
    m.x += t2.z*w[10].x; m.y += t2.z*w[10].y; m.z += t2.z*w[10].z; m.w += t2.z*w[10].w; \
    m.x += t2.w*w[11].x; m.y += t2.w*w[11].y; m.z += t2.w*w[11].z; m.w += t2.w*w[11].w; \
    m.x += t3.x*w[12].x; m.y += t3.x*w[12].y; m.z += t3.x*w[12].z; m.w += t3.x*w[12].w; \
    m.x += t3.y*w[13].x; m.y += t3.y*w[13].y; m.z += t3.y*w[13].z; m.w += t3.y*w[13].w; \
    m.x += t3.z*w[14].x; m.y += t3.z*w[14].y; m.z += t3.z*w[14].z; m.w += t3.z*w[14].w; \
    m.x += t3.w*w[15].x; m.y += t3.w*w[15].y; m.z += t3.w*w[15].z; m.w += t3.w*w[15].w;

__global__ void __launch_bounds__(96, 5)
aggr_kernel(const float* __restrict__ xin,
            const float* __restrict__ We,
            const float* __restrict__ be,
            const float* __restrict__ eps, int l,
            float* __restrict__ aggr) {
    int lane = threadIdx.x & 31;
    int warp = (blockIdx.x * blockDim.x + threadIdx.x) >> 5;
    int nwarps = (gridDim.x * blockDim.x) >> 5;
    int c0 = lane * 4;

    float4 w[ED];
    #pragma unroll
    for (int k = 0; k < ED; k++)
        w[k] = *(const float4*)(We + k * DD + c0);
    float4 bias = *(const float4*)(be + c0);
    float s = 1.0f + eps[l];

    for (int d = warp; d < NN; d += nwarps) {
        float4 xv = *(const float4*)(xin + (size_t)d * DD + c0);
        float4 acc = make_float4(xv.x * s, xv.y * s, xv.z * s, xv.w * s);
        int beg = g_rowptr[d], end = g_rowptr[d + 1];

        if (beg < end) {
            int s0 = g_src[beg];
            int s1 = (beg + 1 < end) ? g_src[beg + 1] : 0;
            int j = beg;
            for (; j + 1 < end; j += 2) {
                const float4* p0 = (const float4*)(g_eattr + (size_t)j * ED);
                float4 a0 = p0[0], a1 = p0[1], a2 = p0[2], a3 = p0[3];
                float4 b0 = p0[4], b1 = p0[5], b2 = p0[6], b3 = p0[7];
                float4 xs0 = *(const float4*)(xin + (size_t)s0 * DD + c0);
                float4 xs1 = *(const float4*)(xin + (size_t)s1 * DD + c0);

                // prefetch next iteration's indices (overlaps FMA chain)
                int s0n = 0, s1n = 0;
                if (j + 3 < end) { s0n = g_src[j + 2]; s1n = g_src[j + 3]; }
                else if (j + 2 < end) { s0n = g_src[j + 2]; }

                float4 m0 = bias;
                MCHAIN(m0, a0, a1, a2, a3)
                float4 m1 = bias;
                MCHAIN(m1, b0, b1, b2, b3)

                acc.x += fmaxf(m0.x + xs0.x, 0.0f) + fmaxf(m1.x + xs1.x, 0.0f);
                acc.y += fmaxf(m0.y + xs0.y, 0.0f) + fmaxf(m1.y + xs1.y, 0.0f);
                acc.z += fmaxf(m0.z + xs0.z, 0.0f) + fmaxf(m1.z + xs1.z, 0.0f);
                acc.w += fmaxf(m0.w + xs0.w, 0.0f) + fmaxf(m1.w + xs1.w, 0.0f);

                s0 = s0n; s1 = s1n;
            }
            if (j < end) {   // remainder edge; s0 already holds g_src[j]
                const float4* p0 = (const float4*)(g_eattr + (size_t)j * ED);
                float4 a0 = p0[0], a1 = p0[1], a2 = p0[2], a3 = p0[3];
                float4 xs0 = *(const float4*)(xin + (size_t)s0 * DD + c0);
                float4 m0 = bias;
                MCHAIN(m0, a0, a1, a2, a3)
                acc.x += fmaxf(m0.x + xs0.x, 0.0f);
                acc.y += fmaxf(m0.y + xs0.y, 0.0f);
                acc.z += fmaxf(m0.z + xs0.z, 0.0f);
                acc.w += fmaxf(m0.w + xs0.w, 0.0f);
            }
        }
        *(float4*)(aggr + (size_t)d * DD + c0) = acc;
    }
}

// ---------------------------------------------------------------------------
// Fused node MLP — bf16 3-product, m16n8k16, persistent, 512 threads.
// NEW: next tile's A prefetched into registers during epilogue 2 so the
// global load latency overlaps stores + barrier.
// ---------------------------------------------------------------------------
#define P2 68
#define MLP_TILES ((NN + 127) / 128)     // 391
#define MLP_SMEM_WORDS (6 * 128 * P2 + 256)
#define MLP_SMEM_BYTES (MLP_SMEM_WORDS * 4)

__global__ void __launch_bounds__(512)
mlp_kernel(const float* __restrict__ A,
           const float* __restrict__ W1g,
           const float* __restrict__ b1g,
           const float* __restrict__ W2g,
           const float* __restrict__ b2g,
           float* __restrict__ C) {
    extern __shared__ unsigned um[];
    unsigned* uAhi  = um;
    unsigned* uAmid = um + 128 * P2;
    unsigned* uW1hi = um + 2 * 128 * P2;
    unsigned* uW1mid= um + 3 * 128 * P2;
    unsigned* uW2hi = um + 4 * 128 * P2;
    unsigned* uW2mid= um + 5 * 128 * P2;
    float* sb1 = (float*)(um + 6 * 128 * P2);
    float* sb2 = sb1 + 128;

    int tid = threadIdx.x;

    // One-time: split weights into packed bf16x2 (transposed: [n][k2])
    for (int i = tid; i < 64 * 128; i += 512) {
        int k2 = i >> 7, n = i & 127;     // coalesced over n
        float w0 = W1g[(2 * k2) * 128 + n];
        float w1 = W1g[(2 * k2 + 1) * 128 + n];
        unsigned h, m;
        bf16split2(w0, w1, h, m);
        uW1hi[n * P2 + k2] = h; uW1mid[n * P2 + k2] = m;
        w0 = W2g[(2 * k2) * 128 + n];
        w1 = W2g[(2 * k2 + 1) * 128 + n];
        bf16split2(w0, w1, h, m);
        uW2hi[n * P2 + k2] = h; uW2mid[n * P2 + k2] = m;
    }
    if (tid < 128) { sb1[tid] = b1g[tid]; sb2[tid] = b2g[tid]; }

    int lane = tid & 31, wid = tid >> 5;
    int g = lane >> 2, c = lane & 3;
    int wm = wid & 3, wn = wid >> 2;      // warp grid 4 x 4
    int mrow = wm * 32;
    int ncol = wn * 32;

    int ar = tid >> 5, aq = tid & 31;     // this thread's A-load row/quad base

    int tile = blockIdx.x;
    float4 pref[8];
    if (tile < MLP_TILES) {
        int row0 = tile * 128;
        #pragma unroll
        for (int ii = 0; ii < 8; ii++) {
            int r = ar + ii * 16;         // 512 threads cover 128 rows x 32 quads
            int gr = row0 + r;
            pref[ii] = (gr < NN) ? ((const float4*)(A + (size_t)gr * DD))[aq]
                                 : make_float4(0.f, 0.f, 0.f, 0.f);
        }
    }
    __syncthreads();   // weights ready
    if (tile < MLP_TILES) {
        #pragma unroll
        for (int ii = 0; ii < 8; ii++) {
            int r = ar + ii * 16;
            float4 v = pref[ii];
            unsigned h0, m0, h1, m1;
            bf16split2(v.x, v.y, h0, m0);
            bf16split2(v.z, v.w, h1, m1);
            uAhi [r * P2 + 2 * aq]     = h0;
            uAhi [r * P2 + 2 * aq + 1] = h1;
            uAmid[r * P2 + 2 * aq]     = m0;
            uAmid[r * P2 + 2 * aq + 1] = m1;
        }
    }
    __syncthreads();

    for (; tile < MLP_TILES; ) {
        int row0 = tile * 128;

        float acc[2][4][4];
        #pragma unroll
        for (int mt = 0; mt < 2; mt++)
            #pragma unroll
            for (int j = 0; j < 4; j++)
                #pragma unroll
                for (int q = 0; q < 4; q++) acc[mt][j][q] = 0.0f;

        // ---- GEMM1: A @ W1 (8 k-steps of 16) ----
        #pragma unroll 1
        for (int s = 0; s < 8; s++) {
            int k0 = s * 8;
            unsigned bh[4][2], bm[4][2];
            #pragma unroll
            for (int j = 0; j < 4; j++) {
                const unsigned* ph = uW1hi  + (ncol + 8 * j + g) * P2 + k0;
                const unsigned* pm = uW1mid + (ncol + 8 * j + g) * P2 + k0;
                bh[j][0] = ph[c]; bh[j][1] = ph[c + 4];
                bm[j][0] = pm[c]; bm[j][1] = pm[c + 4];
            }
            unsigned ah[2][4], am[2][4];
            #pragma unroll
            for (int mt = 0; mt < 2; mt++) {
                int r = mrow + mt * 16 + g;
                const unsigned* p0 = uAhi  + r * P2 + k0;
                const unsigned* p1 = uAhi  + (r + 8) * P2 + k0;
                const unsigned* q0 = uAmid + r * P2 + k0;
                const unsigned* q1 = uAmid + (r + 8) * P2 + k0;
                ah[mt][0] = p0[c]; ah[mt][1] = p1[c];
                ah[mt][2] = p0[c + 4]; ah[mt][3] = p1[c + 4];
                am[mt][0] = q0[c]; am[mt][1] = q1[c];
                am[mt][2] = q0[c + 4]; am[mt][3] = q1[c + 4];
            }
            #pragma unroll
            for (int mt = 0; mt < 2; mt++)
                #pragma unroll
                for (int j = 0; j < 4; j++) mma_bf16(acc[mt][j], ah[mt], bh[j]);
            #pragma unroll
            for (int mt = 0; mt < 2; mt++)
                #pragma unroll
                for (int j = 0; j < 4; j++) mma_bf16(acc[mt][j], ah[mt], bm[j]);
            #pragma unroll
            for (int mt = 0; mt < 2; mt++)
                #pragma unroll
                for (int j = 0; j < 4; j++) mma_bf16(acc[mt][j], am[mt], bh[j]);
        }
        __syncthreads();   // all warps done reading uA*

        // ---- epilogue 1: H = gelu_exact(D1 + b1) -> split into uAhi/uAmid --
        #pragma unroll
        for (int mt = 0; mt < 2; mt++) {
            int r = mrow + mt * 16 + g;
            #pragma unroll
            for (int j = 0; j < 4; j++) {
                int col = ncol + 8 * j + 2 * c;
                int k2 = (ncol >> 1) + 4 * j + c;
                float h0 = acc[mt][j][0] + sb1[col];
                float h1 = acc[mt][j][1] + sb1[col + 1];
                float h2 = acc[mt][j][2] + sb1[col];
                float h3 = acc[mt][j][3] + sb1[col + 1];
                h0 = 0.5f * h0 * (1.0f + erff(h0 * 0.70710678118654752f));
                h1 = 0.5f * h1 * (1.0f + erff(h1 * 0.70710678118654752f));
                h2 = 0.5f * h2 * (1.0f + erff(h2 * 0.70710678118654752f));
                h3 = 0.5f * h3 * (1.0f + erff(h3 * 0.70710678118654752f));
                unsigned hh, mm;
                bf16split2(h0, h1, hh, mm);
                uAhi[r * P2 + k2] = hh; uAmid[r * P2 + k2] = mm;
                bf16split2(h2, h3, hh, mm);
                uAhi[(r + 8) * P2 + k2] = hh; uAmid[(r + 8) * P2 + k2] = mm;
                acc[mt][j][0] = 0.0f; acc[mt][j][1] = 0.0f;
                acc[mt][j][2] = 0.0f; acc[mt][j][3] = 0.0f;
            }
        }
        __syncthreads();

        // ---- GEMM2: H @ W2 ----
        #pragma unroll 1
        for (int s = 0; s < 8; s++) {
            int k0 = s * 8;
            unsigned bh[4][2], bm[4][2];
            #pragma unroll
            for (int j = 0; j < 4; j++) {
                const unsigned* ph = uW2hi  + (ncol + 8 * j + g) * P2 + k0;
                const unsigned* pm = uW2mid + (ncol + 8 * j + g) * P2 + k0;
                bh[j][0] = ph[c]; bh[j][1] = ph[c + 4];
                bm[j][0] = pm[c]; bm[j][1] = pm[c + 4];
            }
            unsigned ah[2][4], am[2][4];
            #pragma unroll
            for (int mt = 0; mt < 2; mt++) {
                int r = mrow + mt * 16 + g;
                const unsigned* p0 = uAhi  + r * P2 + k0;
                const unsigned* p1 = uAhi  + (r + 8) * P2 + k0;
                const unsigned* q0 = uAmid + r * P2 + k0;
                const unsigned* q1 = uAmid + (r + 8) * P2 + k0;
                ah[mt][0] = p0[c]; ah[mt][1] = p1[c];
                ah[mt][2] = p0[c + 4]; ah[mt][3] = p1[c + 4];
                am[mt][0] = q0[c]; am[mt][1] = q1[c];
                am[mt][2] = q0[c + 4]; am[mt][3] = q1[c + 4];
            }
            #pragma unroll
            for (int mt = 0; mt < 2; mt++)
                #pragma unroll
                for (int j = 0; j < 4; j++) mma_bf16(acc[mt][j], ah[mt], bh[j]);
            #pragma unroll
            for (int mt = 0; mt < 2; mt++)
                #pragma unroll
                for (int j = 0; j < 4; j++) mma_bf16(acc[mt][j], ah[mt], bm[j]);
            #pragma unroll
            for (int mt = 0; mt < 2; mt++)
                #pragma unroll
                for (int j = 0; j < 4; j++) mma_bf16(acc[mt][j], am[mt], bh[j]);
        }

        // ---- prefetch next tile's A into registers (overlaps epilogue 2) --
        int ntile = tile + gridDim.x;
        bool has_next = (ntile < MLP_TILES);
        if (has_next) {
            int nrow0 = ntile * 128;
            #pragma unroll
            for (int ii = 0; ii < 8; ii++) {
                int r = ar + ii * 16;
                int gr = nrow0 + r;
                pref[ii] = (gr < NN) ? ((const float4*)(A + (size_t)gr * DD))[aq]
                                     : make_float4(0.f, 0.f, 0.f, 0.f);
            }
        }

        // ---- epilogue 2: C = D2 + b2 ----
        #pragma unroll
        for (int mt = 0; mt < 2; mt++) {
            int r = mrow + mt * 16 + g;
            int gr0 = row0 + r, gr1 = row0 + r + 8;
            #pragma unroll
            for (int j = 0; j < 4; j++) {
                int col = ncol + 8 * j + 2 * c;
                if (gr0 < NN)
                    *(float2*)(C + (size_t)gr0 * DD + col) =
                        make_float2(acc[mt][j][0] + sb2[col],
                                    acc[mt][j][1] + sb2[col + 1]);
                if (gr1 < NN)
                    *(float2*)(C + (size_t)gr1 * DD + col) =
                        make_float2(acc[mt][j][2] + sb2[col],
                                    acc[mt][j][3] + sb2[col + 1]);
            }
        }

        if (has_next) {
            __syncthreads();   // all warps done reading uA* (GEMM2 finished)
            #pragma unroll
            for (int ii = 0; ii < 8; ii++) {
                int r = ar + ii * 16;
                float4 v = pref[ii];
                unsigned h0, m0, h1, m1;
                bf16split2(v.x, v.y, h0, m0);
                bf16split2(v.z, v.w, h1, m1);
                uAhi [r * P2 + 2 * aq]     = h0;
                uAhi [r * P2 + 2 * aq + 1] = h1;
                uAmid[r * P2 + 2 * aq]     = m0;
                uAmid[r * P2 + 2 * aq + 1] = m1;
            }
            __syncthreads();
        }
        tile = ntile;
    }
}

// ---------------------------------------------------------------------------
// Launch
// ---------------------------------------------------------------------------
extern "C" void kernel_launch(void* const* d_in, const int* in_sizes, int n_in,
                              void* d_out, int out_size) {
    const float* x         = (const float*)d_in[0];
    const float* edge_attr = (const float*)d_in[1];
    const float* W1        = (const float*)d_in[2];
    const float* b1        = (const float*)d_in[3];
    const float* W2        = (const float*)d_in[4];
    const float* b2        = (const float*)d_in[5];
    const float* We        = (const float*)d_in[6];
    const float* be        = (const float*)d_in[7];
    const float* eps       = (const float*)d_in[8];
    const void*  edge_idx  = d_in[9];
    float* out = (float*)d_out;

    float *bufA, *bufB;
    cudaGetSymbolAddress((void**)&bufA, g_bufA);
    cudaGetSymbolAddress((void**)&bufB, g_bufB);

    cudaFuncSetAttribute(mlp_kernel,
                         cudaFuncAttributeMaxDynamicSharedMemorySize,
                         MLP_SMEM_BYTES);

    // ---- CSR build + attr pre-sort (once per launch) ----
    detect_idx_kernel<<<1, 32>>>((const long long*)edge_idx);
    zero_cnt_kernel<<<(NN + 255) / 256, 256>>>();
    hist_kernel<<<(NE + 255) / 256, 256>>>(edge_idx);
    local_scan_kernel<<<SCAN_NBLK, 1024>>>();
    scan_sums_kernel<<<1, 64>>>();
    add_off_kernel<<<SCAN_NBLK, 1024>>>();
    scatter_fused_kernel<<<(NE + 255) / 256, 256>>>(edge_idx, edge_attr);

    const int aggr_blocks = (NN * 32 + 95) / 96;   // warp per node, 96-thr blocks

    const float* xin = x;
    for (int l = 0; l < 3; l++) {
        float* aggr = (l == 1) ? bufB : bufA;
        float* xout = (l == 0) ? bufA : ((l == 1) ? bufB : out);

        aggr_kernel<<<aggr_blocks, 96>>>(xin, We + l * ED * DD,
                                         be + l * DD, eps, l, aggr);
        mlp_kernel<<<148, 512, MLP_SMEM_BYTES>>>(
            aggr, W1 + l * DD * DD, b1 + l * DD,
            W2 + l * DD * DD, b2 + l * DD, xout);
        xin = xout;
    }
}